// round 1
// baseline (speedup 1.0000x reference)
#include <cuda_runtime.h>
#include <math_constants.h>

#define NB   16
#define NSQ  1024
#define NSE  1024
#define NCIN 256
#define NDK  64
#define NH   8
#define NFD  512   // H * DK = H * DV

// ---------------- scratch (static device allocations; allowed) ----------------
static __device__ float g_qh[NB * NSQ * NFD];   // [b, s, h, d]
static __device__ float g_kh[NB * NSE * NFD];   // [b, t, h, d]
static __device__ float g_vh[NB * NSE * NFD];   // [b, t, h, e]
static __device__ float g_o [NB * NSQ * NFD];   // [b, s, h*64+e]
static __device__ float g_p [NB * NSQ * NCIN];  // [b, s, c]
static __device__ float g_sum[NCIN];
static __device__ float g_sumsq[NCIN];
static __device__ float g_scale[NCIN];
static __device__ float g_shift[NCIN];

// ---------------- QKV projection GEMM: C[m,n] = sum_k A[m,k] * W[n,k] ----------------
// M=16384, N=512, K=256. 64x64 block tile, 4x4 micro-tile, 256 threads.
__global__ void __launch_bounds__(256) gemm_proj(const float* __restrict__ A,
                                                 const float* __restrict__ W,
                                                 int sel) {
    __shared__ float As[16][64];
    __shared__ float Ws[16][64];
    const int tx = threadIdx.x, ty = threadIdx.y;
    const int tid = ty * 16 + tx;
    const int m0 = blockIdx.y * 64, n0 = blockIdx.x * 64;
    const int lr = tid >> 2;          // 0..63 row loaded
    const int lk = (tid & 3) * 4;     // k offset within 16-wide tile
    const int K = 256, N = NFD;

    float* __restrict__ C = (sel == 0) ? g_qh : (sel == 1) ? g_kh : g_vh;

    float acc[4][4] = {};
    const float* Arow = A + (size_t)(m0 + lr) * K + lk;
    const float* Wrow = W + (size_t)(n0 + lr) * K + lk;

    for (int k0 = 0; k0 < K; k0 += 16) {
        float4 a = *(const float4*)(Arow + k0);
        float4 w = *(const float4*)(Wrow + k0);
        __syncthreads();
        As[lk + 0][lr] = a.x; As[lk + 1][lr] = a.y;
        As[lk + 2][lr] = a.z; As[lk + 3][lr] = a.w;
        Ws[lk + 0][lr] = w.x; Ws[lk + 1][lr] = w.y;
        Ws[lk + 2][lr] = w.z; Ws[lk + 3][lr] = w.w;
        __syncthreads();
#pragma unroll
        for (int kk = 0; kk < 16; kk++) {
            float4 av = *(const float4*)&As[kk][ty * 4];
            float4 wv = *(const float4*)&Ws[kk][tx * 4];
            const float aa[4] = {av.x, av.y, av.z, av.w};
            const float ww[4] = {wv.x, wv.y, wv.z, wv.w};
#pragma unroll
            for (int i = 0; i < 4; i++)
#pragma unroll
                for (int j = 0; j < 4; j++) acc[i][j] += aa[i] * ww[j];
        }
    }
#pragma unroll
    for (int i = 0; i < 4; i++) {
        float4 r = make_float4(acc[i][0], acc[i][1], acc[i][2], acc[i][3]);
        *(float4*)&C[(size_t)(m0 + ty * 4 + i) * N + n0 + tx * 4] = r;
    }
}

// ---------------- Flash attention: one block per (b, h, 64-row q tile) ----------------
__global__ void __launch_bounds__(256) attn_kernel() {
    __shared__ float Qt[64 * 64];    // k-major: Qt[k*64 + r], pre-scaled
    __shared__ float KPt[64 * 64];   // K tile (k-major), later aliased as swizzled P
    __shared__ float Vt[64 * 64];    // natural: Vt[t*64 + e]

    const int tx = threadIdx.x, ty = threadIdx.y;
    const int tid = ty * 16 + tx;
    const int b = blockIdx.z, h = blockIdx.y;
    const int q0 = blockIdx.x * 64;
    const int lr = tid >> 2;         // 0..63 global row loaded
    const int lf = tid & 3;          // float4 group base

    const float* Qb = g_qh + ((size_t)(b * NSQ + q0)) * NFD + h * NDK;
    const float* Kb = g_kh + ((size_t)b * NSE) * NFD + h * NDK;
    const float* Vb = g_vh + ((size_t)b * NSE) * NFD + h * NDK;

    // load Q tile transposed (k-major), fold in 1/sqrt(DK)
#pragma unroll
    for (int i = 0; i < 4; i++) {
        int f = lf + 4 * i;  // 0..15
        float4 v = *(const float4*)(Qb + (size_t)lr * NFD + f * 4);
        Qt[(f * 4 + 0) * 64 + lr] = v.x * 0.125f;
        Qt[(f * 4 + 1) * 64 + lr] = v.y * 0.125f;
        Qt[(f * 4 + 2) * 64 + lr] = v.z * 0.125f;
        Qt[(f * 4 + 3) * 64 + lr] = v.w * 0.125f;
    }

    float mrow[4], lrow[4], O[4][4];
#pragma unroll
    for (int i = 0; i < 4; i++) {
        mrow[i] = -CUDART_INF_F; lrow[i] = 0.f;
#pragma unroll
        for (int j = 0; j < 4; j++) O[i][j] = 0.f;
    }

    for (int t0 = 0; t0 < NSE; t0 += 64) {
        __syncthreads();  // previous iter done with Vt/KPt (and Qt stores visible, iter0)
        // load K (transposed, k-major) and V (natural)
#pragma unroll
        for (int i = 0; i < 4; i++) {
            int f = lf + 4 * i;
            float4 kv = *(const float4*)(Kb + (size_t)(t0 + lr) * NFD + f * 4);
            KPt[(f * 4 + 0) * 64 + lr] = kv.x;
            KPt[(f * 4 + 1) * 64 + lr] = kv.y;
            KPt[(f * 4 + 2) * 64 + lr] = kv.z;
            KPt[(f * 4 + 3) * 64 + lr] = kv.w;
            float4 vv = *(const float4*)(Vb + (size_t)(t0 + lr) * NFD + f * 4);
            *(float4*)&Vt[lr * 64 + f * 4] = vv;
        }
        __syncthreads();

        // S = (Q*scale) @ K^T  (64x64, this thread: rows ty*4.., cols tx*4..)
        float s[4][4] = {};
#pragma unroll 16
        for (int k = 0; k < 64; k++) {
            float4 av = *(const float4*)&Qt[k * 64 + ty * 4];
            float4 bv = *(const float4*)&KPt[k * 64 + tx * 4];
            const float aa[4] = {av.x, av.y, av.z, av.w};
            const float bb[4] = {bv.x, bv.y, bv.z, bv.w};
#pragma unroll
            for (int i = 0; i < 4; i++)
#pragma unroll
                for (int j = 0; j < 4; j++) s[i][j] += aa[i] * bb[j];
        }

        // online softmax update (row groups span 16 lanes: lane = (ty&1)*16 + tx)
#pragma unroll
        for (int i = 0; i < 4; i++) {
            float mx = fmaxf(fmaxf(s[i][0], s[i][1]), fmaxf(s[i][2], s[i][3]));
#pragma unroll
            for (int w = 8; w; w >>= 1)
                mx = fmaxf(mx, __shfl_xor_sync(0xffffffffu, mx, w, 16));
            float mn = fmaxf(mrow[i], mx);
            float fac = __expf(mrow[i] - mn);
            float rs = 0.f;
#pragma unroll
            for (int j = 0; j < 4; j++) { s[i][j] = __expf(s[i][j] - mn); rs += s[i][j]; }
#pragma unroll
            for (int w = 8; w; w >>= 1)
                rs += __shfl_xor_sync(0xffffffffu, rs, w, 16);
            lrow[i] = lrow[i] * fac + rs;
            mrow[i] = mn;
#pragma unroll
            for (int j = 0; j < 4; j++) O[i][j] *= fac;
        }

        __syncthreads();  // everyone done reading K from KPt
        // store P transposed into KPt with XOR swizzle: P[t][r] at col-group (r>>2)^(t>>2)
#pragma unroll
        for (int j = 0; j < 4; j++) {
            int t = tx * 4 + j;                      // t>>2 == tx
            int col = ((ty ^ tx) & 15) << 2;
#pragma unroll
            for (int i = 0; i < 4; i++) KPt[t * 64 + col + i] = s[i][j];
        }
        __syncthreads();

        // O += P @ V
#pragma unroll 16
        for (int t = 0; t < 64; t++) {
            int col = ((ty ^ (t >> 2)) & 15) << 2;
            float4 pv = *(const float4*)&KPt[t * 64 + col];       // P[t][ty*4..+3]
            float4 vv = *(const float4*)&Vt[t * 64 + tx * 4];     // V[t][tx*4..+3]
            const float pp[4] = {pv.x, pv.y, pv.z, pv.w};
            const float vvv[4] = {vv.x, vv.y, vv.z, vv.w};
#pragma unroll
            for (int i = 0; i < 4; i++)
#pragma unroll
                for (int j = 0; j < 4; j++) O[i][j] += pp[i] * vvv[j];
        }
    }

    // epilogue: O /= l, write o[b, s, h*64+e]
    float* Ob = g_o + ((size_t)(b * NSQ + q0)) * NFD + h * NDK;
#pragma unroll
    for (int i = 0; i < 4; i++) {
        float inv = 1.0f / lrow[i];
        float4 r = make_float4(O[i][0] * inv, O[i][1] * inv, O[i][2] * inv, O[i][3] * inv);
        *(float4*)(Ob + (size_t)(ty * 4 + i) * NFD + tx * 4) = r;
    }
}

// ---------------- output projection + BN statistics ----------------
// p[m, c] = sum_f o[m, f] * Wp[c, f];  M=16384, N=256, K=512
__global__ void __launch_bounds__(256) outproj_kernel(const float* __restrict__ Wp) {
    __shared__ float As[16][64];
    __shared__ float Ws[16][64];
    __shared__ float red[16][64];
    const int tx = threadIdx.x, ty = threadIdx.y;
    const int tid = ty * 16 + tx;
    const int m0 = blockIdx.y * 64, n0 = blockIdx.x * 64;
    const int lr = tid >> 2;
    const int lk = (tid & 3) * 4;
    const int K = NFD, N = NCIN;

    float acc[4][4] = {};
    const float* Arow = g_o + (size_t)(m0 + lr) * K + lk;
    const float* Wrow = Wp + (size_t)(n0 + lr) * K + lk;

    for (int k0 = 0; k0 < K; k0 += 16) {
        float4 a = *(const float4*)(Arow + k0);
        float4 w = *(const float4*)(Wrow + k0);
        __syncthreads();
        As[lk + 0][lr] = a.x; As[lk + 1][lr] = a.y;
        As[lk + 2][lr] = a.z; As[lk + 3][lr] = a.w;
        Ws[lk + 0][lr] = w.x; Ws[lk + 1][lr] = w.y;
        Ws[lk + 2][lr] = w.z; Ws[lk + 3][lr] = w.w;
        __syncthreads();
#pragma unroll
        for (int kk = 0; kk < 16; kk++) {
            float4 av = *(const float4*)&As[kk][ty * 4];
            float4 wv = *(const float4*)&Ws[kk][tx * 4];
            const float aa[4] = {av.x, av.y, av.z, av.w};
            const float ww[4] = {wv.x, wv.y, wv.z, wv.w};
#pragma unroll
            for (int i = 0; i < 4; i++)
#pragma unroll
                for (int j = 0; j < 4; j++) acc[i][j] += aa[i] * ww[j];
        }
    }

    // write p
#pragma unroll
    for (int i = 0; i < 4; i++) {
        float4 r = make_float4(acc[i][0], acc[i][1], acc[i][2], acc[i][3]);
        *(float4*)&g_p[(size_t)(m0 + ty * 4 + i) * N + n0 + tx * 4] = r;
    }

    // per-channel partial sums over this block's 64 rows
    float cs[4], cq[4];
#pragma unroll
    for (int j = 0; j < 4; j++) {
        cs[j] = acc[0][j] + acc[1][j] + acc[2][j] + acc[3][j];
        cq[j] = acc[0][j] * acc[0][j] + acc[1][j] * acc[1][j]
              + acc[2][j] * acc[2][j] + acc[3][j] * acc[3][j];
    }
    __syncthreads();
#pragma unroll
    for (int j = 0; j < 4; j++) red[ty][tx * 4 + j] = cs[j];
    __syncthreads();
    if (tid < 64) {
        float v = 0.f;
#pragma unroll
        for (int r = 0; r < 16; r++) v += red[r][tid];
        atomicAdd(&g_sum[n0 + tid], v);
    }
    __syncthreads();
#pragma unroll
    for (int j = 0; j < 4; j++) red[ty][tx * 4 + j] = cq[j];
    __syncthreads();
    if (tid < 64) {
        float v = 0.f;
#pragma unroll
        for (int r = 0; r < 16; r++) v += red[r][tid];
        atomicAdd(&g_sumsq[n0 + tid], v);
    }
}

// ---------------- small kernels ----------------
__global__ void zero_stats() {
    g_sum[threadIdx.x] = 0.f;
    g_sumsq[threadIdx.x] = 0.f;
}

__global__ void bnprep_kernel(const float* __restrict__ gamma,
                              const float* __restrict__ beta) {
    int c = threadIdx.x;
    const float inv_nm = 1.0f / (float)(NB * NSQ);
    float mean = g_sum[c] * inv_nm;
    float var = g_sumsq[c] * inv_nm - mean * mean;
    float sc = gamma[c] * rsqrtf(var + 1e-5f);
    g_scale[c] = sc;
    g_shift[c] = beta[c] - mean * sc;
}

__global__ void __launch_bounds__(256) finalize_kernel(float* __restrict__ out) {
    int idx = blockIdx.x * 256 + threadIdx.x;
    int c = threadIdx.x;  // C=256 == blockDim, row-major
    float y = g_p[idx] * g_scale[c] + g_shift[c];
    out[idx] = (y >= 0.f) ? y : 0.01f * y;
}

// ---------------- launch ----------------
extern "C" void kernel_launch(void* const* d_in, const int* in_sizes, int n_in,
                              void* d_out, int out_size) {
    const float* x     = (const float*)d_in[0];  // [16,1024,256]
    const float* q     = (const float*)d_in[1];  // [16,1024,256]
    const float* Wq    = (const float*)d_in[2];  // [8,64,256] -> [512,256]
    const float* Wk    = (const float*)d_in[3];
    const float* Wv    = (const float*)d_in[4];
    const float* Wp    = (const float*)d_in[5];  // [256,512]
    const float* gamma = (const float*)d_in[6];
    const float* beta  = (const float*)d_in[7];
    float* out = (float*)d_out;

    dim3 blk(16, 16);
    zero_stats<<<1, 256>>>();
    gemm_proj<<<dim3(8, 256), blk>>>(q, Wq, 0);
    gemm_proj<<<dim3(8, 256), blk>>>(x, Wk, 1);
    gemm_proj<<<dim3(8, 256), blk>>>(x, Wv, 2);
    attn_kernel<<<dim3(NSQ / 64, NH, NB), blk>>>();
    outproj_kernel<<<dim3(NCIN / 64, NB * NSQ / 64), blk>>>(Wp);
    bnprep_kernel<<<1, 256>>>(gamma, beta);
    finalize_kernel<<<NB * NSQ, 256>>>(out);
}

// round 4
// speedup vs baseline: 1.3017x; 1.3017x over previous
#include <cuda_runtime.h>
#include <math_constants.h>

#define NB   16
#define NSQ  1024
#define NSE  1024
#define NCIN 256
#define NH   8
#define NFD  512

// ---------------- scratch ----------------
static __device__ float g_qh[NB * NSQ * NFD];
static __device__ float g_kh[NB * NSE * NFD];
static __device__ float g_vh[NB * NSE * NFD];
static __device__ float g_o [NB * NSQ * NFD];
static __device__ float g_p [NB * NSQ * NCIN];
static __device__ float g_sum[NCIN];
static __device__ float g_sumsq[NCIN];
static __device__ float g_scale[NCIN];
static __device__ float g_shift[NCIN];

__device__ __forceinline__ void cp16(void* dst, const void* src) {
    unsigned d = (unsigned)__cvta_generic_to_shared(dst);
    asm volatile("cp.async.ca.shared.global [%0], [%1], 16;" :: "r"(d), "l"(src));
}

// ---------------- fused QKV projection: 128x128 tile, 8x8 split micro ----------------
__global__ void __launch_bounds__(256, 2) gemm_qkv(const float* __restrict__ q,
                                                   const float* __restrict__ x,
                                                   const float* __restrict__ Wq,
                                                   const float* __restrict__ Wk,
                                                   const float* __restrict__ Wv) {
    __shared__ float As[8][128];
    __shared__ float Bs[8][128];
    const int tid = threadIdx.x;
    const int tx = tid & 15, ty = tid >> 4;
    const int m0 = blockIdx.y * 128, n0 = blockIdx.x * 128;
    const int z = blockIdx.z;
    const float* A = (z == 0) ? q : x;
    const float* W = (z == 0) ? Wq : (z == 1) ? Wk : Wv;
    float* C = (z == 0) ? g_qh : (z == 1) ? g_kh : g_vh;
    const int lr = tid >> 1, lc = (tid & 1) * 4;

    const float* Ap = A + (size_t)(m0 + lr) * 256 + lc;
    const float* Wp = W + (size_t)(n0 + lr) * 256 + lc;
    float4 pa = *(const float4*)Ap;
    float4 pb = *(const float4*)Wp;
    float acc[2][2][4][4] = {};

    for (int k0 = 0; k0 < 256; k0 += 8) {
        As[lc + 0][lr] = pa.x; As[lc + 1][lr] = pa.y;
        As[lc + 2][lr] = pa.z; As[lc + 3][lr] = pa.w;
        Bs[lc + 0][lr] = pb.x; Bs[lc + 1][lr] = pb.y;
        Bs[lc + 2][lr] = pb.z; Bs[lc + 3][lr] = pb.w;
        __syncthreads();
        if (k0 + 8 < 256) {
            pa = *(const float4*)(Ap + k0 + 8);
            pb = *(const float4*)(Wp + k0 + 8);
        }
#pragma unroll
        for (int kk = 0; kk < 8; kk++) {
            float4 a0 = *(const float4*)&As[kk][ty * 4];
            float4 a1 = *(const float4*)&As[kk][64 + ty * 4];
            float4 b0 = *(const float4*)&Bs[kk][tx * 4];
            float4 b1 = *(const float4*)&Bs[kk][64 + tx * 4];
            float av[2][4] = {{a0.x, a0.y, a0.z, a0.w}, {a1.x, a1.y, a1.z, a1.w}};
            float bv[2][4] = {{b0.x, b0.y, b0.z, b0.w}, {b1.x, b1.y, b1.z, b1.w}};
#pragma unroll
            for (int ri = 0; ri < 2; ri++)
#pragma unroll
                for (int i = 0; i < 4; i++)
#pragma unroll
                    for (int ci = 0; ci < 2; ci++)
#pragma unroll
                        for (int j = 0; j < 4; j++)
                            acc[ri][ci][i][j] += av[ri][i] * bv[ci][j];
        }
        __syncthreads();
    }
#pragma unroll
    for (int ri = 0; ri < 2; ri++)
#pragma unroll
        for (int i = 0; i < 4; i++) {
            size_t row = m0 + ri * 64 + ty * 4 + i;
#pragma unroll
            for (int ci = 0; ci < 2; ci++) {
                float4 r = make_float4(acc[ri][ci][i][0], acc[ri][ci][i][1],
                                       acc[ri][ci][i][2], acc[ri][ci][i][3]);
                *(float4*)&C[row * NFD + n0 + ci * 64 + tx * 4] = r;
            }
        }
}

// ---------------- flash attention: S^T = K Q^T formulation ----------------
__global__ void __launch_bounds__(128, 4) attn_kernel() {
    __shared__ float Qd[64 * 64];   // [d][r] transposed Q, pre-scaled
    __shared__ float KP[64 * 64];   // K natural [t][d] | red/facs | Pt [t][r]
    __shared__ float Vn[64 * 64];   // V natural [t][e]

    const int tid = threadIdx.x;
    const int tx = tid & 15, ty = tid >> 4;   // 16 x 8
    const int b = blockIdx.z, h = blockIdx.y, q0 = blockIdx.x * 64;

    const float* Qg = g_qh + ((size_t)(b * NSQ + q0)) * NFD + h * 64;
    const float* Kg = g_kh + ((size_t)b * NSE) * NFD + h * 64;
    const float* Vg = g_vh + ((size_t)b * NSE) * NFD + h * 64;

    // Q load + transpose to d-major, fold 1/sqrt(64)
    {
        const int rr = tid >> 4;
        const int f4 = (tid & 15) * 4;
#pragma unroll
        for (int i = 0; i < 8; i++) {
            int r = i * 8 + rr;
            float4 v = *(const float4*)(Qg + (size_t)r * NFD + f4);
            Qd[(f4 + 0) * 64 + r] = v.x * 0.125f;
            Qd[(f4 + 1) * 64 + r] = v.y * 0.125f;
            Qd[(f4 + 2) * 64 + r] = v.z * 0.125f;
            Qd[(f4 + 3) * 64 + r] = v.w * 0.125f;
        }
    }

    float m_[4], l_[4], O[8][4];
#pragma unroll
    for (int j = 0; j < 4; j++) { m_[j] = -CUDART_INF_F; l_[j] = 0.f; }
#pragma unroll
    for (int i = 0; i < 8; i++)
#pragma unroll
        for (int j = 0; j < 4; j++) O[i][j] = 0.f;

    for (int t0 = 0; t0 < NSE; t0 += 64) {
        // async-load K, V tiles (natural layout, straight copies)
        {
            const int rr = tid >> 4;
            const int f4 = (tid & 15) * 4;
#pragma unroll
            for (int i = 0; i < 8; i++) {
                int t = i * 8 + rr;
                cp16(&KP[t * 64 + f4], Kg + (size_t)(t0 + t) * NFD + f4);
                cp16(&Vn[t * 64 + f4], Vg + (size_t)(t0 + t) * NFD + f4);
            }
            asm volatile("cp.async.commit_group;");
            asm volatile("cp.async.wait_group 0;" ::: "memory");
        }
        __syncthreads();                                   // S1

        // GEMM1: st[t=ty*8+i][r=tx*4+j] = K[t,:] . Qscaled[r,:]
        float st[8][4];
#pragma unroll
        for (int i = 0; i < 8; i++)
#pragma unroll
            for (int j = 0; j < 4; j++) st[i][j] = 0.f;
#pragma unroll 2
        for (int d4 = 0; d4 < 64; d4 += 4) {
            float4 b0 = *(const float4*)&Qd[(d4 + 0) * 64 + tx * 4];
            float4 b1 = *(const float4*)&Qd[(d4 + 1) * 64 + tx * 4];
            float4 b2 = *(const float4*)&Qd[(d4 + 2) * 64 + tx * 4];
            float4 b3 = *(const float4*)&Qd[(d4 + 3) * 64 + tx * 4];
#pragma unroll
            for (int i = 0; i < 8; i++) {
                float4 a = *(const float4*)&KP[(ty * 8 + i) * 64 + d4];
                st[i][0] += a.x * b0.x + a.y * b1.x + a.z * b2.x + a.w * b3.x;
                st[i][1] += a.x * b0.y + a.y * b1.y + a.z * b2.y + a.w * b3.y;
                st[i][2] += a.x * b0.z + a.y * b1.z + a.z * b2.z + a.w * b3.z;
                st[i][3] += a.x * b0.w + a.y * b1.w + a.z * b2.w + a.w * b3.w;
            }
        }

        // cross-warp softmax over t (partials per thread, reduce via smem)
        float pm[4];
#pragma unroll
        for (int j = 0; j < 4; j++) {
            float a = fmaxf(fmaxf(st[0][j], st[1][j]), fmaxf(st[2][j], st[3][j]));
            float c = fmaxf(fmaxf(st[4][j], st[5][j]), fmaxf(st[6][j], st[7][j]));
            pm[j] = fmaxf(a, c);
        }
        __syncthreads();                                   // S2 (GEMM1 done with KP)
        *(float4*)&KP[ty * 64 + tx * 4] = make_float4(pm[0], pm[1], pm[2], pm[3]);
        __syncthreads();                                   // S3
        float4 mx = *(const float4*)&KP[tx * 4];
#pragma unroll
        for (int yy = 1; yy < 8; yy++) {
            float4 t = *(const float4*)&KP[yy * 64 + tx * 4];
            mx.x = fmaxf(mx.x, t.x); mx.y = fmaxf(mx.y, t.y);
            mx.z = fmaxf(mx.z, t.z); mx.w = fmaxf(mx.w, t.w);
        }
        float fac[4], ps[4];
        {
            float mn0 = fmaxf(m_[0], mx.x), mn1 = fmaxf(m_[1], mx.y);
            float mn2 = fmaxf(m_[2], mx.z), mn3 = fmaxf(m_[3], mx.w);
            fac[0] = __expf(m_[0] - mn0); fac[1] = __expf(m_[1] - mn1);
            fac[2] = __expf(m_[2] - mn2); fac[3] = __expf(m_[3] - mn3);
            m_[0] = mn0; m_[1] = mn1; m_[2] = mn2; m_[3] = mn3;
        }
#pragma unroll
        for (int j = 0; j < 4; j++) ps[j] = 0.f;
#pragma unroll
        for (int i = 0; i < 8; i++)
#pragma unroll
            for (int j = 0; j < 4; j++) {
                st[i][j] = __expf(st[i][j] - m_[j]);
                ps[j] += st[i][j];
            }
        __syncthreads();                                   // S4
        *(float4*)&KP[ty * 64 + tx * 4] = make_float4(ps[0], ps[1], ps[2], ps[3]);
        if (ty == 0)
            *(float4*)&KP[512 + tx * 4] = make_float4(fac[0], fac[1], fac[2], fac[3]);
        __syncthreads();                                   // S5
        {
            float4 rs = *(const float4*)&KP[tx * 4];
#pragma unroll
            for (int yy = 1; yy < 8; yy++) {
                float4 t = *(const float4*)&KP[yy * 64 + tx * 4];
                rs.x += t.x; rs.y += t.y; rs.z += t.z; rs.w += t.w;
            }
            l_[0] = l_[0] * fac[0] + rs.x;
            l_[1] = l_[1] * fac[1] + rs.y;
            l_[2] = l_[2] * fac[2] + rs.z;
            l_[3] = l_[3] * fac[3] + rs.w;
        }
        // rescale O by this tile's fac for its own rows
#pragma unroll
        for (int i = 0; i < 8; i++) {
            float f = KP[512 + ty * 8 + i];
#pragma unroll
            for (int j = 0; j < 4; j++) O[i][j] *= f;
        }
        __syncthreads();                                   // S6
        // store P^T (t-major) — conflict-free float4 stores
#pragma unroll
        for (int i = 0; i < 8; i++)
            *(float4*)&KP[(ty * 8 + i) * 64 + tx * 4] =
                make_float4(st[i][0], st[i][1], st[i][2], st[i][3]);
        __syncthreads();                                   // S7

        // PV: O[r=ty*8+i][e=tx*4+j] += P[r][t] V[t][e]
#pragma unroll 4
        for (int t = 0; t < 64; t++) {
            float4 p0 = *(const float4*)&KP[t * 64 + ty * 8];
            float4 p1 = *(const float4*)&KP[t * 64 + ty * 8 + 4];
            float4 v  = *(const float4*)&Vn[t * 64 + tx * 4];
            O[0][0] += p0.x * v.x; O[0][1] += p0.x * v.y; O[0][2] += p0.x * v.z; O[0][3] += p0.x * v.w;
            O[1][0] += p0.y * v.x; O[1][1] += p0.y * v.y; O[1][2] += p0.y * v.z; O[1][3] += p0.y * v.w;
            O[2][0] += p0.z * v.x; O[2][1] += p0.z * v.y; O[2][2] += p0.z * v.z; O[2][3] += p0.z * v.w;
            O[3][0] += p0.w * v.x; O[3][1] += p0.w * v.y; O[3][2] += p0.w * v.z; O[3][3] += p0.w * v.w;
            O[4][0] += p1.x * v.x; O[4][1] += p1.x * v.y; O[4][2] += p1.x * v.z; O[4][3] += p1.x * v.w;
            O[5][0] += p1.y * v.x; O[5][1] += p1.y * v.y; O[5][2] += p1.y * v.z; O[5][3] += p1.y * v.w;
            O[6][0] += p1.z * v.x; O[6][1] += p1.z * v.y; O[6][2] += p1.z * v.z; O[6][3] += p1.z * v.w;
            O[7][0] += p1.w * v.x; O[7][1] += p1.w * v.y; O[7][2] += p1.w * v.z; O[7][3] += p1.w * v.w;
        }
        __syncthreads();                                   // S8 (KP, Vn free)
    }

    // epilogue: broadcast l to O-row owners, normalize, store
    if (ty == 0)
        *(float4*)&KP[tx * 4] = make_float4(l_[0], l_[1], l_[2], l_[3]);
    __syncthreads();
    float* Og = g_o + ((size_t)(b * NSQ + q0)) * NFD + h * 64;
#pragma unroll
    for (int i = 0; i < 8; i++) {
        float inv = 1.0f / KP[ty * 8 + i];
        *(float4*)(Og + (size_t)(ty * 8 + i) * NFD + tx * 4) =
            make_float4(O[i][0] * inv, O[i][1] * inv, O[i][2] * inv, O[i][3] * inv);
    }
}

// ---------------- output projection + BN stats: 128x128 tile ----------------
__global__ void __launch_bounds__(256, 2) outproj_kernel(const float* __restrict__ Wp) {
    __shared__ float sh[2048];
    float (*As)[128] = (float(*)[128])sh;
    float (*Bs)[128] = (float(*)[128])(sh + 1024);
    const int tid = threadIdx.x;
    const int tx = tid & 15, ty = tid >> 4;
    const int m0 = blockIdx.y * 128, n0 = blockIdx.x * 128;
    const int lr = tid >> 1, lc = (tid & 1) * 4;

    const float* Ap = g_o + (size_t)(m0 + lr) * NFD + lc;
    const float* Wr = Wp + (size_t)(n0 + lr) * NFD + lc;
    float4 pa = *(const float4*)Ap;
    float4 pb = *(const float4*)Wr;
    float acc[2][2][4][4] = {};

    for (int k0 = 0; k0 < NFD; k0 += 8) {
        As[lc + 0][lr] = pa.x; As[lc + 1][lr] = pa.y;
        As[lc + 2][lr] = pa.z; As[lc + 3][lr] = pa.w;
        Bs[lc + 0][lr] = pb.x; Bs[lc + 1][lr] = pb.y;
        Bs[lc + 2][lr] = pb.z; Bs[lc + 3][lr] = pb.w;
        __syncthreads();
        if (k0 + 8 < NFD) {
            pa = *(const float4*)(Ap + k0 + 8);
            pb = *(const float4*)(Wr + k0 + 8);
        }
#pragma unroll
        for (int kk = 0; kk < 8; kk++) {
            float4 a0 = *(const float4*)&As[kk][ty * 4];
            float4 a1 = *(const float4*)&As[kk][64 + ty * 4];
            float4 b0 = *(const float4*)&Bs[kk][tx * 4];
            float4 b1 = *(const float4*)&Bs[kk][64 + tx * 4];
            float av[2][4] = {{a0.x, a0.y, a0.z, a0.w}, {a1.x, a1.y, a1.z, a1.w}};
            float bv[2][4] = {{b0.x, b0.y, b0.z, b0.w}, {b1.x, b1.y, b1.z, b1.w}};
#pragma unroll
            for (int ri = 0; ri < 2; ri++)
#pragma unroll
                for (int i = 0; i < 4; i++)
#pragma unroll
                    for (int ci = 0; ci < 2; ci++)
#pragma unroll
                        for (int j = 0; j < 4; j++)
                            acc[ri][ci][i][j] += av[ri][i] * bv[ci][j];
        }
        __syncthreads();
    }
#pragma unroll
    for (int ri = 0; ri < 2; ri++)
#pragma unroll
        for (int i = 0; i < 4; i++) {
            size_t row = m0 + ri * 64 + ty * 4 + i;
#pragma unroll
            for (int ci = 0; ci < 2; ci++) {
                float4 r = make_float4(acc[ri][ci][i][0], acc[ri][ci][i][1],
                                       acc[ri][ci][i][2], acc[ri][ci][i][3]);
                *(float4*)&g_p[row * NCIN + n0 + ci * 64 + tx * 4] = r;
            }
        }

    // per-channel partial stats over this block's 128 rows
    float cs[2][4] = {}, cq[2][4] = {};
#pragma unroll
    for (int ri = 0; ri < 2; ri++)
#pragma unroll
        for (int ci = 0; ci < 2; ci++)
#pragma unroll
            for (int i = 0; i < 4; i++)
#pragma unroll
                for (int j = 0; j < 4; j++) {
                    float v = acc[ri][ci][i][j];
                    cs[ci][j] += v;
                    cq[ci][j] += v * v;
                }
    __syncthreads();
#pragma unroll
    for (int ci = 0; ci < 2; ci++)
        *(float4*)&sh[ty * 128 + ci * 64 + tx * 4] =
            make_float4(cs[ci][0], cs[ci][1], cs[ci][2], cs[ci][3]);
    __syncthreads();
    if (tid < 128) {
        float v = 0.f;
#pragma unroll
        for (int yy = 0; yy < 16; yy++) v += sh[yy * 128 + tid];
        atomicAdd(&g_sum[n0 + tid], v);
    }
    __syncthreads();
#pragma unroll
    for (int ci = 0; ci < 2; ci++)
        *(float4*)&sh[ty * 128 + ci * 64 + tx * 4] =
            make_float4(cq[ci][0], cq[ci][1], cq[ci][2], cq[ci][3]);
    __syncthreads();
    if (tid < 128) {
        float v = 0.f;
#pragma unroll
        for (int yy = 0; yy < 16; yy++) v += sh[yy * 128 + tid];
        atomicAdd(&g_sumsq[n0 + tid], v);
    }
}

// ---------------- small kernels ----------------
__global__ void zero_stats() {
    g_sum[threadIdx.x] = 0.f;
    g_sumsq[threadIdx.x] = 0.f;
}

__global__ void bnprep_kernel(const float* __restrict__ gamma,
                              const float* __restrict__ beta) {
    int c = threadIdx.x;
    const float inv_nm = 1.0f / (float)(NB * NSQ);
    float mean = g_sum[c] * inv_nm;
    float var = g_sumsq[c] * inv_nm - mean * mean;
    float sc = gamma[c] * rsqrtf(var + 1e-5f);
    g_scale[c] = sc;
    g_shift[c] = beta[c] - mean * sc;
}

__global__ void __launch_bounds__(256) finalize_kernel(float* __restrict__ out) {
    int idx = blockIdx.x * 256 + threadIdx.x;
    int c = threadIdx.x;
    float y = g_p[idx] * g_scale[c] + g_shift[c];
    out[idx] = (y >= 0.f) ? y : 0.01f * y;
}

// ---------------- launch ----------------
extern "C" void kernel_launch(void* const* d_in, const int* in_sizes, int n_in,
                              void* d_out, int out_size) {
    const float* x     = (const float*)d_in[0];
    const float* q     = (const float*)d_in[1];
    const float* Wq    = (const float*)d_in[2];
    const float* Wk    = (const float*)d_in[3];
    const float* Wv    = (const float*)d_in[4];
    const float* Wp    = (const float*)d_in[5];
    const float* gamma = (const float*)d_in[6];
    const float* beta  = (const float*)d_in[7];
    float* out = (float*)d_out;

    zero_stats<<<1, 256>>>();
    gemm_qkv<<<dim3(4, 128, 3), 256>>>(q, x, Wq, Wk, Wv);
    attn_kernel<<<dim3(NSQ / 64, NH, NB), 128>>>();
    outproj_kernel<<<dim3(2, 128), 256>>>(Wp);
    bnprep_kernel<<<1, 256>>>(gamma, beta);
    finalize_kernel<<<NB * NSQ, 256>>>(out);
}

// round 6
// speedup vs baseline: 2.3500x; 1.8053x over previous
#include <cuda_runtime.h>
#include <math_constants.h>

#define NB   16
#define NSQ  1024
#define NSE  1024
#define NCIN 256
#define NH   8
#define NFD  512

// ---------------- scratch ----------------
// g_qh: Q A-fragment-major  [b][h][rowtile(64)][kstep(8)][lane(32)][4]
// g_kh: K B-fragment-major  [b][h][keytile(16)][ntile(8)][p(4)][lane(32)][4]
// g_vh: V B-fragment-major  [b][h][keytile(16)][ntile(8)][p(4)][lane(32)][4]
static __device__ float g_qh[NB * NSQ * NFD];
static __device__ float g_kh[NB * NSE * NFD];
static __device__ float g_vh[NB * NSE * NFD];
static __device__ float g_o [NB * NSQ * NFD];
static __device__ float g_p [NB * NSQ * NCIN];
static __device__ float g_sum[NCIN];
static __device__ float g_sumsq[NCIN];
static __device__ float g_scale[NCIN];
static __device__ float g_shift[NCIN];

__device__ __forceinline__ void cp16(void* dst, const void* src) {
    unsigned d = (unsigned)__cvta_generic_to_shared(dst);
    asm volatile("cp.async.ca.shared.global [%0], [%1], 16;" :: "r"(d), "l"(src));
}

__device__ __forceinline__ unsigned tf32r(float x) {
    unsigned u;
    asm("cvt.rna.tf32.f32 %0, %1;" : "=r"(u) : "f"(x));
    return u;
}

__device__ __forceinline__ void mma8(float4& d, uint4 a, unsigned b0, unsigned b1) {
    asm volatile(
        "mma.sync.aligned.m16n8k8.row.col.f32.tf32.tf32.f32 "
        "{%0,%1,%2,%3}, {%4,%5,%6,%7}, {%8,%9}, {%0,%1,%2,%3};"
        : "+f"(d.x), "+f"(d.y), "+f"(d.z), "+f"(d.w)
        : "r"(a.x), "r"(a.y), "r"(a.z), "r"(a.w), "r"(b0), "r"(b1));
}

// ---------------- fused QKV projection: SIMT GEMM, fragment-major epilogue ----------------
__global__ void __launch_bounds__(256, 2) gemm_qkv(const float* __restrict__ q,
                                                   const float* __restrict__ x,
                                                   const float* __restrict__ Wq,
                                                   const float* __restrict__ Wk,
                                                   const float* __restrict__ Wv) {
    __shared__ float As[8][128];
    __shared__ float Bs[8][128];
    const int tid = threadIdx.x;
    const int tx = tid & 15, ty = tid >> 4;
    const int m0 = blockIdx.y * 128, n0 = blockIdx.x * 128;
    const int z = blockIdx.z;
    const float* A = (z == 0) ? q : x;
    const float* W = (z == 0) ? Wq : (z == 1) ? Wk : Wv;
    const int lr = tid >> 1, lc = (tid & 1) * 4;

    const float* Ap = A + (size_t)(m0 + lr) * 256 + lc;
    const float* Wr = W + (size_t)(n0 + lr) * 256 + lc;
    float4 pa = *(const float4*)Ap;
    float4 pb = *(const float4*)Wr;
    float acc[2][2][4][4] = {};

    for (int k0 = 0; k0 < 256; k0 += 8) {
        As[lc + 0][lr] = pa.x; As[lc + 1][lr] = pa.y;
        As[lc + 2][lr] = pa.z; As[lc + 3][lr] = pa.w;
        Bs[lc + 0][lr] = pb.x; Bs[lc + 1][lr] = pb.y;
        Bs[lc + 2][lr] = pb.z; Bs[lc + 3][lr] = pb.w;
        __syncthreads();
        if (k0 + 8 < 256) {
            pa = *(const float4*)(Ap + k0 + 8);
            pb = *(const float4*)(Wr + k0 + 8);
        }
#pragma unroll
        for (int kk = 0; kk < 8; kk++) {
            float4 a0 = *(const float4*)&As[kk][ty * 4];
            float4 a1 = *(const float4*)&As[kk][64 + ty * 4];
            float4 b0 = *(const float4*)&Bs[kk][tx * 4];
            float4 b1 = *(const float4*)&Bs[kk][64 + tx * 4];
            float av[2][4] = {{a0.x, a0.y, a0.z, a0.w}, {a1.x, a1.y, a1.z, a1.w}};
            float bv[2][4] = {{b0.x, b0.y, b0.z, b0.w}, {b1.x, b1.y, b1.z, b1.w}};
#pragma unroll
            for (int ri = 0; ri < 2; ri++)
#pragma unroll
                for (int i = 0; i < 4; i++)
#pragma unroll
                    for (int ci = 0; ci < 2; ci++)
#pragma unroll
                        for (int j = 0; j < 4; j++)
                            acc[ri][ci][i][j] += av[ri][i] * bv[ci][j];
        }
        __syncthreads();
    }

    // fragment-major scatter epilogue (tf32-rounded; Q pre-scaled by 1/sqrt(64))
    unsigned* Qo = (unsigned*)g_qh;
    unsigned* Ko = (unsigned*)g_kh;
    unsigned* Vo = (unsigned*)g_vh;
#pragma unroll
    for (int ri = 0; ri < 2; ri++)
#pragma unroll
        for (int i = 0; i < 4; i++) {
            int mrow = m0 + ri * 64 + ty * 4 + i;
            int bb = mrow >> 10, ss = mrow & 1023;
#pragma unroll
            for (int ci = 0; ci < 2; ci++)
#pragma unroll
                for (int j = 0; j < 4; j++) {
                    int ncol = n0 + ci * 64 + tx * 4 + j;
                    int hh = ncol >> 6, dd = ncol & 63;
                    float val = acc[ri][ci][i][j];
                    if (z == 0) {
                        unsigned bits = tf32r(val * 0.125f);
                        size_t ad = ((((size_t)(bb * 8 + hh) * 64 + (ss >> 4)) * 8 + (dd >> 3)) * 32
                                     + ((ss & 7) * 4 + (dd & 3))) * 4
                                    + ((ss >> 3) & 1) + 2 * ((dd >> 2) & 1);
                        Qo[ad] = bits;
                    } else if (z == 1) {
                        unsigned bits = tf32r(val);
                        size_t ad = (size_t)((bb * 8 + hh) * 16 + (ss >> 6)) * 4096
                                    + ((ss >> 3) & 7) * 512 + (dd >> 4) * 128
                                    + ((ss & 7) * 4 + (dd & 3)) * 4 + ((dd & 15) >> 2);
                        Ko[ad] = bits;
                    } else {
                        unsigned bits = tf32r(val);
                        size_t ad = (size_t)((bb * 8 + hh) * 16 + (ss >> 6)) * 4096
                                    + (dd >> 3) * 512 + ((ss >> 4) & 3) * 128
                                    + ((dd & 7) * 4 + (ss & 3)) * 4 + ((ss >> 2) & 3);
                        Vo[ad] = bits;
                    }
                }
        }
}

// ---------------- flash attention on tensor cores (tf32 mma.sync) ----------------
// block: 128 threads = 4 warps; warp = 16 q-rows x 64 keys; block = 64 q-rows.
__global__ void __launch_bounds__(128, 3) attn_mma() {
    __shared__ unsigned Ks[4096];      // 16KB: K key-tile, fragment-major
    __shared__ unsigned Vs[4096];      // 16KB: V key-tile, fragment-major
    __shared__ unsigned Pb[4][1024];   // 4KB per warp: P A-fragments [kstep][chunk^][4]

    const int tid = threadIdx.x;
    const int w = tid >> 5, l = tid & 31;
    const int g = l >> 2, qq = l & 3;
    const int b = blockIdx.z, h = blockIdx.y;
    const int q0 = blockIdx.x * 64;
    const int rt = (q0 >> 4) + w;

    // hoist Q A-fragments (pre-rounded, pre-scaled)
    const unsigned* Qg = (const unsigned*)g_qh + (size_t)(((b * 8 + h) * 64 + rt) * 8) * 128;
    uint4 qa[8];
#pragma unroll
    for (int kk = 0; kk < 8; kk++)
        qa[kk] = *(const uint4*)(Qg + kk * 128 + l * 4);

    const unsigned* Kg = (const unsigned*)g_kh + (size_t)((b * 8 + h) * 16) * 4096;
    const unsigned* Vg = (const unsigned*)g_vh + (size_t)((b * 8 + h) * 16) * 4096;

    float4 o[8];
#pragma unroll
    for (int nt = 0; nt < 8; nt++) o[nt] = make_float4(0.f, 0.f, 0.f, 0.f);
    float m0_ = -CUDART_INF_F, m1_ = -CUDART_INF_F, l0_ = 0.f, l1_ = 0.f;

    for (int kt = 0; kt < 16; kt++) {
        // linear cp.async of fragment-major tiles
#pragma unroll
        for (int i = 0; i < 8; i++) {
            cp16(&Ks[(i * 128 + tid) * 4], Kg + (size_t)kt * 4096 + (i * 128 + tid) * 4);
            cp16(&Vs[(i * 128 + tid) * 4], Vg + (size_t)kt * 4096 + (i * 128 + tid) * 4);
        }
        asm volatile("cp.async.commit_group;");
        asm volatile("cp.async.wait_group 0;" ::: "memory");
        __syncthreads();

        // S = Qscaled @ K^T : per-warp 16x64, fragments
        float4 s[8];
#pragma unroll
        for (int nt = 0; nt < 8; nt++) {
            s[nt] = make_float4(0.f, 0.f, 0.f, 0.f);
            uint4 k0 = *(const uint4*)&Ks[nt * 512 + (0 * 32 + l) * 4];
            uint4 k1 = *(const uint4*)&Ks[nt * 512 + (1 * 32 + l) * 4];
            uint4 k2 = *(const uint4*)&Ks[nt * 512 + (2 * 32 + l) * 4];
            uint4 k3 = *(const uint4*)&Ks[nt * 512 + (3 * 32 + l) * 4];
            mma8(s[nt], qa[0], k0.x, k0.y); mma8(s[nt], qa[1], k0.z, k0.w);
            mma8(s[nt], qa[2], k1.x, k1.y); mma8(s[nt], qa[3], k1.z, k1.w);
            mma8(s[nt], qa[4], k2.x, k2.y); mma8(s[nt], qa[5], k2.z, k2.w);
            mma8(s[nt], qa[6], k3.x, k3.y); mma8(s[nt], qa[7], k3.z, k3.w);
        }

        // online softmax: rows g (x,y) and g+8 (z,w); rows live in 4-lane quads
        float mx0 = fmaxf(s[0].x, s[0].y), mx1 = fmaxf(s[0].z, s[0].w);
#pragma unroll
        for (int nt = 1; nt < 8; nt++) {
            mx0 = fmaxf(mx0, fmaxf(s[nt].x, s[nt].y));
            mx1 = fmaxf(mx1, fmaxf(s[nt].z, s[nt].w));
        }
        mx0 = fmaxf(mx0, __shfl_xor_sync(0xffffffffu, mx0, 1));
        mx0 = fmaxf(mx0, __shfl_xor_sync(0xffffffffu, mx0, 2));
        mx1 = fmaxf(mx1, __shfl_xor_sync(0xffffffffu, mx1, 1));
        mx1 = fmaxf(mx1, __shfl_xor_sync(0xffffffffu, mx1, 2));
        float nm0 = fmaxf(m0_, mx0), nm1 = fmaxf(m1_, mx1);
        float f0 = __expf(m0_ - nm0), f1 = __expf(m1_ - nm1);
        m0_ = nm0; m1_ = nm1;

        // P = exp(S - m), tf32-rounded; row sums from the ROUNDED values
        float rs0 = 0.f, rs1 = 0.f;
        const int cA = 4 * g + ((2 * qq) & 3);
        const int cB = 4 * g + ((2 * qq + 1) & 3);
        const int phA = (cA ^ (cA >> 3)) * 4 + 2 * (qq >> 1);
        const int phB = (cB ^ (cB >> 3)) * 4 + 2 * (qq >> 1);
#pragma unroll
        for (int nt = 0; nt < 8; nt++) {
            unsigned p0 = tf32r(__expf(s[nt].x - nm0));
            unsigned p1 = tf32r(__expf(s[nt].y - nm0));
            unsigned p2 = tf32r(__expf(s[nt].z - nm1));
            unsigned p3 = tf32r(__expf(s[nt].w - nm1));
            rs0 += __uint_as_float(p0) + __uint_as_float(p1);
            rs1 += __uint_as_float(p2) + __uint_as_float(p3);
            uint2 vA; vA.x = p0; vA.y = p2;   // (a-reg idx 2dh, 2dh+1)
            uint2 vB; vB.x = p1; vB.y = p3;
            *(uint2*)&Pb[w][nt * 128 + phA] = vA;
            *(uint2*)&Pb[w][nt * 128 + phB] = vB;
        }
        rs0 += __shfl_xor_sync(0xffffffffu, rs0, 1);
        rs0 += __shfl_xor_sync(0xffffffffu, rs0, 2);
        rs1 += __shfl_xor_sync(0xffffffffu, rs1, 1);
        rs1 += __shfl_xor_sync(0xffffffffu, rs1, 2);
        l0_ = l0_ * f0 + rs0;
        l1_ = l1_ * f1 + rs1;

        // rescale O
#pragma unroll
        for (int nt = 0; nt < 8; nt++) {
            o[nt].x *= f0; o[nt].y *= f0; o[nt].z *= f1; o[nt].w *= f1;
        }
        __syncwarp();

        // reload P as A-fragments (warp-private, swizzled, conflict-free)
        const int cr = (l ^ (l >> 3)) * 4;
        uint4 pa[8];
#pragma unroll
        for (int kk = 0; kk < 8; kk++)
            pa[kk] = *(const uint4*)&Pb[w][kk * 128 + cr];

        // O += P @ V
#pragma unroll
        for (int nt = 0; nt < 8; nt++) {
            uint4 v0 = *(const uint4*)&Vs[nt * 512 + (0 * 32 + l) * 4];
            uint4 v1 = *(const uint4*)&Vs[nt * 512 + (1 * 32 + l) * 4];
            uint4 v2 = *(const uint4*)&Vs[nt * 512 + (2 * 32 + l) * 4];
            uint4 v3 = *(const uint4*)&Vs[nt * 512 + (3 * 32 + l) * 4];
            mma8(o[nt], pa[0], v0.x, v0.y); mma8(o[nt], pa[1], v0.z, v0.w);
            mma8(o[nt], pa[2], v1.x, v1.y); mma8(o[nt], pa[3], v1.z, v1.w);
            mma8(o[nt], pa[4], v2.x, v2.y); mma8(o[nt], pa[5], v2.z, v2.w);
            mma8(o[nt], pa[6], v3.x, v3.y); mma8(o[nt], pa[7], v3.z, v3.w);
        }
        __syncthreads();   // done with Ks/Vs before next tile's cp.async
    }

    // epilogue: normalize, write natural layout for outproj
    float inv0 = 1.0f / l0_, inv1 = 1.0f / l1_;
    float* Og = g_o + (size_t)(b * NSQ + q0 + w * 16) * NFD + h * 64;
#pragma unroll
    for (int nt = 0; nt < 8; nt++) {
        *(float2*)&Og[(size_t)g * NFD + nt * 8 + 2 * qq] =
            make_float2(o[nt].x * inv0, o[nt].y * inv0);
        *(float2*)&Og[(size_t)(g + 8) * NFD + nt * 8 + 2 * qq] =
            make_float2(o[nt].z * inv1, o[nt].w * inv1);
    }
}

// ---------------- output projection + BN stats: 128x128 tile ----------------
__global__ void __launch_bounds__(256, 2) outproj_kernel(const float* __restrict__ Wp) {
    __shared__ float sh[2048];
    float (*As)[128] = (float(*)[128])sh;
    float (*Bs)[128] = (float(*)[128])(sh + 1024);
    const int tid = threadIdx.x;
    const int tx = tid & 15, ty = tid >> 4;
    const int m0 = blockIdx.y * 128, n0 = blockIdx.x * 128;
    const int lr = tid >> 1, lc = (tid & 1) * 4;

    const float* Ap = g_o + (size_t)(m0 + lr) * NFD + lc;
    const float* Wr = Wp + (size_t)(n0 + lr) * NFD + lc;
    float4 pa = *(const float4*)Ap;
    float4 pb = *(const float4*)Wr;
    float acc[2][2][4][4] = {};

    for (int k0 = 0; k0 < NFD; k0 += 8) {
        As[lc + 0][lr] = pa.x; As[lc + 1][lr] = pa.y;
        As[lc + 2][lr] = pa.z; As[lc + 3][lr] = pa.w;
        Bs[lc + 0][lr] = pb.x; Bs[lc + 1][lr] = pb.y;
        Bs[lc + 2][lr] = pb.z; Bs[lc + 3][lr] = pb.w;
        __syncthreads();
        if (k0 + 8 < NFD) {
            pa = *(const float4*)(Ap + k0 + 8);
            pb = *(const float4*)(Wr + k0 + 8);
        }
#pragma unroll
        for (int kk = 0; kk < 8; kk++) {
            float4 a0 = *(const float4*)&As[kk][ty * 4];
            float4 a1 = *(const float4*)&As[kk][64 + ty * 4];
            float4 b0 = *(const float4*)&Bs[kk][tx * 4];
            float4 b1 = *(const float4*)&Bs[kk][64 + tx * 4];
            float av[2][4] = {{a0.x, a0.y, a0.z, a0.w}, {a1.x, a1.y, a1.z, a1.w}};
            float bv[2][4] = {{b0.x, b0.y, b0.z, b0.w}, {b1.x, b1.y, b1.z, b1.w}};
#pragma unroll
            for (int ri = 0; ri < 2; ri++)
#pragma unroll
                for (int i = 0; i < 4; i++)
#pragma unroll
                    for (int ci = 0; ci < 2; ci++)
#pragma unroll
                        for (int j = 0; j < 4; j++)
                            acc[ri][ci][i][j] += av[ri][i] * bv[ci][j];
        }
        __syncthreads();
    }
#pragma unroll
    for (int ri = 0; ri < 2; ri++)
#pragma unroll
        for (int i = 0; i < 4; i++) {
            size_t row = m0 + ri * 64 + ty * 4 + i;
#pragma unroll
            for (int ci = 0; ci < 2; ci++) {
                float4 r = make_float4(acc[ri][ci][i][0], acc[ri][ci][i][1],
                                       acc[ri][ci][i][2], acc[ri][ci][i][3]);
                *(float4*)&g_p[row * NCIN + n0 + ci * 64 + tx * 4] = r;
            }
        }

    float cs[2][4] = {}, cq[2][4] = {};
#pragma unroll
    for (int ri = 0; ri < 2; ri++)
#pragma unroll
        for (int ci = 0; ci < 2; ci++)
#pragma unroll
            for (int i = 0; i < 4; i++)
#pragma unroll
                for (int j = 0; j < 4; j++) {
                    float v = acc[ri][ci][i][j];
                    cs[ci][j] += v;
                    cq[ci][j] += v * v;
                }
    __syncthreads();
#pragma unroll
    for (int ci = 0; ci < 2; ci++)
        *(float4*)&sh[ty * 128 + ci * 64 + tx * 4] =
            make_float4(cs[ci][0], cs[ci][1], cs[ci][2], cs[ci][3]);
    __syncthreads();
    if (tid < 128) {
        float v = 0.f;
#pragma unroll
        for (int yy = 0; yy < 16; yy++) v += sh[yy * 128 + tid];
        atomicAdd(&g_sum[n0 + tid], v);
    }
    __syncthreads();
#pragma unroll
    for (int ci = 0; ci < 2; ci++)
        *(float4*)&sh[ty * 128 + ci * 64 + tx * 4] =
            make_float4(cq[ci][0], cq[ci][1], cq[ci][2], cq[ci][3]);
    __syncthreads();
    if (tid < 128) {
        float v = 0.f;
#pragma unroll
        for (int yy = 0; yy < 16; yy++) v += sh[yy * 128 + tid];
        atomicAdd(&g_sumsq[n0 + tid], v);
    }
}

// ---------------- small kernels ----------------
__global__ void zero_stats() {
    g_sum[threadIdx.x] = 0.f;
    g_sumsq[threadIdx.x] = 0.f;
}

__global__ void bnprep_kernel(const float* __restrict__ gamma,
                              const float* __restrict__ beta) {
    int c = threadIdx.x;
    const float inv_nm = 1.0f / (float)(NB * NSQ);
    float mean = g_sum[c] * inv_nm;
    float var = g_sumsq[c] * inv_nm - mean * mean;
    float sc = gamma[c] * rsqrtf(var + 1e-5f);
    g_scale[c] = sc;
    g_shift[c] = beta[c] - mean * sc;
}

__global__ void __launch_bounds__(256) finalize_kernel(float* __restrict__ out) {
    int idx = blockIdx.x * 256 + threadIdx.x;
    int c = threadIdx.x;
    float y = g_p[idx] * g_scale[c] + g_shift[c];
    out[idx] = (y >= 0.f) ? y : 0.01f * y;
}

// ---------------- launch ----------------
extern "C" void kernel_launch(void* const* d_in, const int* in_sizes, int n_in,
                              void* d_out, int out_size) {
    const float* x     = (const float*)d_in[0];
    const float* q     = (const float*)d_in[1];
    const float* Wq    = (const float*)d_in[2];
    const float* Wk    = (const float*)d_in[3];
    const float* Wv    = (const float*)d_in[4];
    const float* Wp    = (const float*)d_in[5];
    const float* gamma = (const float*)d_in[6];
    const float* beta  = (const float*)d_in[7];
    float* out = (float*)d_out;

    zero_stats<<<1, 256>>>();
    gemm_qkv<<<dim3(4, 128, 3), 256>>>(q, x, Wq, Wk, Wv);
    attn_mma<<<dim3(NSQ / 64, NH, NB), 128>>>();
    outproj_kernel<<<dim3(2, 128), 256>>>(Wp);
    bnprep_kernel<<<1, 256>>>(gamma, beta);
    finalize_kernel<<<NB * NSQ, 256>>>(out);
}

// round 7
// speedup vs baseline: 3.6982x; 1.5737x over previous
#include <cuda_runtime.h>
#include <math_constants.h>

#define NB   16
#define NSQ  1024
#define NSE  1024
#define NCIN 256
#define NH   8
#define NFD  512

// ---------------- scratch ----------------
// g_qh: Q A-frag layout per (b,h): [tile(s>>4, d>>3)][lane][reg], pre-scaled
// g_kh: K B-frag layout per (b,h); g_vh: V B-frag per (b,h) per 64-key supertile
static __device__ float g_qh[NB * NSQ * NFD];
static __device__ float g_kh[NB * NSE * NFD];
static __device__ float g_vh[NB * NSE * NFD];
static __device__ float g_o [NB * NSQ * NFD];    // A-frag layout, M=16384, K=512 (tf32 bits)
static __device__ float g_p [NB * NSQ * NCIN];
static __device__ float g_qA[NB * NSQ * NCIN];   // q repacked A-frag (K=256)
static __device__ float g_xA[NB * NSE * NCIN];   // x repacked A-frag (K=256)
static __device__ float g_wqB[NFD * NCIN];       // weights B-frag
static __device__ float g_wkB[NFD * NCIN];
static __device__ float g_wvB[NFD * NCIN];
static __device__ float g_wpB[NCIN * NFD];
static __device__ float g_sum[NCIN];
static __device__ float g_sumsq[NCIN];
static __device__ float g_scale[NCIN];
static __device__ float g_shift[NCIN];

__device__ __forceinline__ void cp16(void* dst, const void* src) {
    unsigned d = (unsigned)__cvta_generic_to_shared(dst);
    asm volatile("cp.async.ca.shared.global [%0], [%1], 16;" :: "r"(d), "l"(src));
}

__device__ __forceinline__ unsigned tf32r(float x) {
    unsigned u;
    asm("cvt.rna.tf32.f32 %0, %1;" : "=r"(u) : "f"(x));
    return u;
}

__device__ __forceinline__ void mma8(float4& d, uint4 a, unsigned b0, unsigned b1) {
    asm volatile(
        "mma.sync.aligned.m16n8k8.row.col.f32.tf32.tf32.f32 "
        "{%0,%1,%2,%3}, {%4,%5,%6,%7}, {%8,%9}, {%0,%1,%2,%3};"
        : "+f"(d.x), "+f"(d.y), "+f"(d.z), "+f"(d.w)
        : "r"(a.x), "r"(a.y), "r"(a.z), "r"(a.w), "r"(b0), "r"(b1));
}

// ---------------- repack: activations -> A-frag (K=256), tf32-rounded ----------------
__global__ void __launch_bounds__(256) repackA(const float* __restrict__ in, int which) {
    unsigned* out = (unsigned*)(which ? g_xA : g_qA);
    int u = blockIdx.x * 256 + threadIdx.x;       // uint4 index (1M total)
    int lane = u & 31, tile = u >> 5;
    int tk = tile & 31, tm = tile >> 5;           // K/8 = 32
    int m = tm * 16 + (lane >> 2), k = tk * 8 + (lane & 3);
    const float* p = in + (size_t)m * 256 + k;
    uint4 v;
    v.x = tf32r(p[0]);
    v.y = tf32r(p[8 * 256]);
    v.z = tf32r(p[4]);
    v.w = tf32r(p[8 * 256 + 4]);
    ((uint4*)out)[u] = v;
}

// ---------------- repack: weights -> B-frag, tf32-rounded ----------------
__global__ void __launch_bounds__(256) repackW(const float* __restrict__ Wq,
                                              const float* __restrict__ Wk,
                                              const float* __restrict__ Wv,
                                              const float* __restrict__ Wp) {
    int which = blockIdx.y;
    const float* in = (which == 0) ? Wq : (which == 1) ? Wk : (which == 2) ? Wv : Wp;
    unsigned* out = (unsigned*)((which == 0) ? g_wqB : (which == 1) ? g_wkB
                                : (which == 2) ? g_wvB : g_wpB);
    int K = (which == 3) ? 512 : 256;
    int u = blockIdx.x * 256 + threadIdx.x;       // 32768 uint4 each
    int lane = u & 31, chunk = u >> 5;
    int kp = K >> 4;
    int tkp = chunk % kp, tn = chunk / kp;
    int n = tn * 8 + (lane >> 2), kb = tkp * 16 + (lane & 3);
    const float* p = in + (size_t)n * K + kb;
    uint4 v;
    v.x = tf32r(p[0]);
    v.y = tf32r(p[4]);
    v.z = tf32r(p[8]);
    v.w = tf32r(p[12]);
    ((uint4*)out)[u] = v;
}

// scatter one QKV value into attn's fragment layouts
__device__ __forceinline__ void scatter_qkv(unsigned* out, int z, int m, int n, float val) {
    int b = m >> 10, s = m & 1023;
    int h = n >> 6, d = n & 63;
    size_t base = (size_t)(b * 8 + h) << 16;
    size_t ad;
    unsigned bits;
    if (z == 0) {
        bits = tf32r(val * 0.125f);
        ad = base + (size_t)(((s >> 4) * 8 + (d >> 3)) << 7)
             + (((s & 7) * 4 + (d & 3)) << 2) + ((s >> 3) & 1) + (((d >> 2) & 1) << 1);
    } else if (z == 1) {
        bits = tf32r(val);
        ad = base + (size_t)((s >> 3) << 9) + ((d >> 4) << 7)
             + (((s & 7) * 4 + (d & 3)) << 2) + (((d >> 3) & 1) << 1) + ((d >> 2) & 1);
    } else {
        bits = tf32r(val);
        ad = base + (size_t)((s >> 6) << 12) + ((d >> 3) << 9) + (((s >> 4) & 3) << 7)
             + (((d & 7) * 4 + (s & 3)) << 2) + (((s >> 3) & 1) << 1) + ((s >> 2) & 1);
    }
    out[ad] = bits;
}

// ---------------- QKV projection on tensor cores (K=256) ----------------
// block 128m x 128n, 8 warps (64m x 32n each), k16 double-buffered stages.
__global__ void __launch_bounds__(256, 2) gemm_qkv_mma() {
    __shared__ float As[2][16][128];
    __shared__ float Bs[2][16][128];
    const int tid = threadIdx.x;
    const int w = tid >> 5, l = tid & 31;
    const int wm = w & 1, wn = w >> 1;
    const int g = l >> 2, qq = l & 3;
    const int z = blockIdx.z;
    const int m0 = blockIdx.y * 128, n0 = blockIdx.x * 128;
    const int tm0 = blockIdx.y * 8, tn0 = blockIdx.x * 16;

    const uint4* Ag = (const uint4*)((z == 0) ? g_qA : g_xA);
    const uint4* Bg = (const uint4*)((z == 0) ? g_wqB : (z == 1) ? g_wkB : g_wvB);

#define QKV_LOAD(sst, t16)                                                              \
    {                                                                                   \
        int c0 = tid >> 5, o0 = tid & 31;                                               \
        cp16(&As[sst][c0][o0 * 4],                                                      \
             Ag + ((size_t)((tm0 + (c0 >> 1)) * 32 + (t16) * 2 + (c0 & 1)) * 32 + o0)); \
        int c1 = (tid + 256) >> 5, o1 = tid & 31;                                       \
        cp16(&As[sst][c1][o1 * 4],                                                      \
             Ag + ((size_t)((tm0 + (c1 >> 1)) * 32 + (t16) * 2 + (c1 & 1)) * 32 + o1)); \
        cp16(&Bs[sst][c0][o0 * 4], Bg + ((size_t)((tn0 + c0) * 16 + (t16)) * 32 + o0)); \
        cp16(&Bs[sst][c1][o1 * 4], Bg + ((size_t)((tn0 + c1) * 16 + (t16)) * 32 + o1)); \
        asm volatile("cp.async.commit_group;");                                         \
    }

    float4 c4[4][4];
#pragma unroll
    for (int i = 0; i < 4; i++)
#pragma unroll
        for (int j = 0; j < 4; j++) c4[i][j] = make_float4(0.f, 0.f, 0.f, 0.f);

    QKV_LOAD(0, 0);
    for (int t16 = 0; t16 < 16; t16++) {
        int s = t16 & 1;
        if (t16 + 1 < 16) {
            QKV_LOAD(s ^ 1, t16 + 1);
            asm volatile("cp.async.wait_group 1;" ::: "memory");
        } else {
            asm volatile("cp.async.wait_group 0;" ::: "memory");
        }
        __syncthreads();
        uint4 bv[4];
#pragma unroll
        for (int j = 0; j < 4; j++)
            bv[j] = *(const uint4*)&Bs[s][wn * 4 + j][l * 4];
        {
            uint4 a[4];
#pragma unroll
            for (int i = 0; i < 4; i++)
                a[i] = *(const uint4*)&As[s][(wm * 4 + i) * 2][l * 4];
#pragma unroll
            for (int i = 0; i < 4; i++)
#pragma unroll
                for (int j = 0; j < 4; j++) mma8(c4[i][j], a[i], bv[j].x, bv[j].y);
#pragma unroll
            for (int i = 0; i < 4; i++)
                a[i] = *(const uint4*)&As[s][(wm * 4 + i) * 2 + 1][l * 4];
#pragma unroll
            for (int i = 0; i < 4; i++)
#pragma unroll
                for (int j = 0; j < 4; j++) mma8(c4[i][j], a[i], bv[j].z, bv[j].w);
        }
        __syncthreads();
    }

    unsigned* out = (unsigned*)((z == 0) ? g_qh : (z == 1) ? g_kh : g_vh);
#pragma unroll
    for (int i = 0; i < 4; i++)
#pragma unroll
        for (int j = 0; j < 4; j++) {
            int m = m0 + wm * 64 + i * 16 + g;
            int n = n0 + wn * 32 + j * 8 + 2 * qq;
            scatter_qkv(out, z, m, n, c4[i][j].x);
            scatter_qkv(out, z, m, n + 1, c4[i][j].y);
            scatter_qkv(out, z, m + 8, n, c4[i][j].z);
            scatter_qkv(out, z, m + 8, n + 1, c4[i][j].w);
        }
}

// ---------------- flash attention on tensor cores (tf32 mma.sync) ----------------
__global__ void __launch_bounds__(128, 3) attn_mma() {
    __shared__ unsigned Ks[4096];
    __shared__ unsigned Vs[4096];
    __shared__ unsigned Pb[4][1024];

    const int tid = threadIdx.x;
    const int w = tid >> 5, l = tid & 31;
    const int g = l >> 2, qq = l & 3;
    const int b = blockIdx.z, h = blockIdx.y;
    const int q0 = blockIdx.x * 64;
    const int rt = (q0 >> 4) + w;

    const unsigned* Qg = (const unsigned*)g_qh + (size_t)(((b * 8 + h) * 64 + rt) * 8) * 128;
    uint4 qa[8];
#pragma unroll
    for (int kk = 0; kk < 8; kk++)
        qa[kk] = *(const uint4*)(Qg + kk * 128 + l * 4);

    const unsigned* Kg = (const unsigned*)g_kh + (size_t)((b * 8 + h) * 16) * 4096;
    const unsigned* Vg = (const unsigned*)g_vh + (size_t)((b * 8 + h) * 16) * 4096;

    float4 o[8];
#pragma unroll
    for (int nt = 0; nt < 8; nt++) o[nt] = make_float4(0.f, 0.f, 0.f, 0.f);
    float m0_ = -CUDART_INF_F, m1_ = -CUDART_INF_F, l0_ = 0.f, l1_ = 0.f;

    for (int kt = 0; kt < 16; kt++) {
#pragma unroll
        for (int i = 0; i < 8; i++) {
            cp16(&Ks[(i * 128 + tid) * 4], Kg + (size_t)kt * 4096 + (i * 128 + tid) * 4);
            cp16(&Vs[(i * 128 + tid) * 4], Vg + (size_t)kt * 4096 + (i * 128 + tid) * 4);
        }
        asm volatile("cp.async.commit_group;");
        asm volatile("cp.async.wait_group 0;" ::: "memory");
        __syncthreads();

        float4 s[8];
#pragma unroll
        for (int nt = 0; nt < 8; nt++) {
            s[nt] = make_float4(0.f, 0.f, 0.f, 0.f);
            uint4 k0 = *(const uint4*)&Ks[nt * 512 + (0 * 32 + l) * 4];
            uint4 k1 = *(const uint4*)&Ks[nt * 512 + (1 * 32 + l) * 4];
            uint4 k2 = *(const uint4*)&Ks[nt * 512 + (2 * 32 + l) * 4];
            uint4 k3 = *(const uint4*)&Ks[nt * 512 + (3 * 32 + l) * 4];
            mma8(s[nt], qa[0], k0.x, k0.y); mma8(s[nt], qa[1], k0.z, k0.w);
            mma8(s[nt], qa[2], k1.x, k1.y); mma8(s[nt], qa[3], k1.z, k1.w);
            mma8(s[nt], qa[4], k2.x, k2.y); mma8(s[nt], qa[5], k2.z, k2.w);
            mma8(s[nt], qa[6], k3.x, k3.y); mma8(s[nt], qa[7], k3.z, k3.w);
        }

        float mx0 = fmaxf(s[0].x, s[0].y), mx1 = fmaxf(s[0].z, s[0].w);
#pragma unroll
        for (int nt = 1; nt < 8; nt++) {
            mx0 = fmaxf(mx0, fmaxf(s[nt].x, s[nt].y));
            mx1 = fmaxf(mx1, fmaxf(s[nt].z, s[nt].w));
        }
        mx0 = fmaxf(mx0, __shfl_xor_sync(0xffffffffu, mx0, 1));
        mx0 = fmaxf(mx0, __shfl_xor_sync(0xffffffffu, mx0, 2));
        mx1 = fmaxf(mx1, __shfl_xor_sync(0xffffffffu, mx1, 1));
        mx1 = fmaxf(mx1, __shfl_xor_sync(0xffffffffu, mx1, 2));
        float nm0 = fmaxf(m0_, mx0), nm1 = fmaxf(m1_, mx1);
        float f0 = __expf(m0_ - nm0), f1 = __expf(m1_ - nm1);
        m0_ = nm0; m1_ = nm1;

        float rs0 = 0.f, rs1 = 0.f;
        const int cA = 4 * g + ((2 * qq) & 3);
        const int cB = 4 * g + ((2 * qq + 1) & 3);
        const int phA = (cA ^ (cA >> 3)) * 4 + 2 * (qq >> 1);
        const int phB = (cB ^ (cB >> 3)) * 4 + 2 * (qq >> 1);
#pragma unroll
        for (int nt = 0; nt < 8; nt++) {
            unsigned p0 = tf32r(__expf(s[nt].x - nm0));
            unsigned p1 = tf32r(__expf(s[nt].y - nm0));
            unsigned p2 = tf32r(__expf(s[nt].z - nm1));
            unsigned p3 = tf32r(__expf(s[nt].w - nm1));
            rs0 += __uint_as_float(p0) + __uint_as_float(p1);
            rs1 += __uint_as_float(p2) + __uint_as_float(p3);
            uint2 vA; vA.x = p0; vA.y = p2;
            uint2 vB; vB.x = p1; vB.y = p3;
            *(uint2*)&Pb[w][nt * 128 + phA] = vA;
            *(uint2*)&Pb[w][nt * 128 + phB] = vB;
        }
        rs0 += __shfl_xor_sync(0xffffffffu, rs0, 1);
        rs0 += __shfl_xor_sync(0xffffffffu, rs0, 2);
        rs1 += __shfl_xor_sync(0xffffffffu, rs1, 1);
        rs1 += __shfl_xor_sync(0xffffffffu, rs1, 2);
        l0_ = l0_ * f0 + rs0;
        l1_ = l1_ * f1 + rs1;

#pragma unroll
        for (int nt = 0; nt < 8; nt++) {
            o[nt].x *= f0; o[nt].y *= f0; o[nt].z *= f1; o[nt].w *= f1;
        }
        __syncwarp();

        const int cr = (l ^ (l >> 3)) * 4;
        uint4 pa[8];
#pragma unroll
        for (int kk = 0; kk < 8; kk++)
            pa[kk] = *(const uint4*)&Pb[w][kk * 128 + cr];

#pragma unroll
        for (int nt = 0; nt < 8; nt++) {
            uint4 v0 = *(const uint4*)&Vs[nt * 512 + (0 * 32 + l) * 4];
            uint4 v1 = *(const uint4*)&Vs[nt * 512 + (1 * 32 + l) * 4];
            uint4 v2 = *(const uint4*)&Vs[nt * 512 + (2 * 32 + l) * 4];
            uint4 v3 = *(const uint4*)&Vs[nt * 512 + (3 * 32 + l) * 4];
            mma8(o[nt], pa[0], v0.x, v0.y); mma8(o[nt], pa[1], v0.z, v0.w);
            mma8(o[nt], pa[2], v1.x, v1.y); mma8(o[nt], pa[3], v1.z, v1.w);
            mma8(o[nt], pa[4], v2.x, v2.y); mma8(o[nt], pa[5], v2.z, v2.w);
            mma8(o[nt], pa[6], v3.x, v3.y); mma8(o[nt], pa[7], v3.z, v3.w);
        }
        __syncthreads();
    }

    // epilogue: normalize + write O directly in A-frag layout (tf32) for outproj
    float inv0 = 1.0f / l0_, inv1 = 1.0f / l1_;
    unsigned* Oo = (unsigned*)g_o;
    const int tmrow = b * 64 + (q0 >> 4) + w;
#pragma unroll
    for (int nt = 0; nt < 8; nt++) {
        int k0 = h * 64 + nt * 8 + 2 * qq;
        int tk = k0 >> 3;
        size_t toff = (size_t)(tmrow * 64 + tk) * 128;
        int rbase = ((k0 >> 2) & 1) * 2;
        uint2 vx; vx.x = tf32r(o[nt].x * inv0); vx.y = tf32r(o[nt].z * inv1);
        *(uint2*)&Oo[toff + (g * 4 + (k0 & 3)) * 4 + rbase] = vx;
        uint2 vy; vy.x = tf32r(o[nt].y * inv0); vy.y = tf32r(o[nt].w * inv1);
        *(uint2*)&Oo[toff + (g * 4 + ((k0 + 1) & 3)) * 4 + rbase] = vy;
    }
}

// ---------------- output projection on tensor cores (K=512) + BN stats ----------------
__global__ void __launch_bounds__(256, 2) outproj_mma() {
    __shared__ float As[2][16][128];
    __shared__ float Bs[2][16][128];
    const int tid = threadIdx.x;
    const int w = tid >> 5, l = tid & 31;
    const int wm = w & 1, wn = w >> 1;
    const int g = l >> 2, qq = l & 3;
    const int m0 = blockIdx.y * 128, n0 = blockIdx.x * 128;
    const int tm0 = blockIdx.y * 8, tn0 = blockIdx.x * 16;

    const uint4* Ag = (const uint4*)g_o;
    const uint4* Bg = (const uint4*)g_wpB;

#define OP_LOAD(sst, t16)                                                               \
    {                                                                                   \
        int c0 = tid >> 5, o0 = tid & 31;                                               \
        cp16(&As[sst][c0][o0 * 4],                                                      \
             Ag + ((size_t)((tm0 + (c0 >> 1)) * 64 + (t16) * 2 + (c0 & 1)) * 32 + o0)); \
        int c1 = (tid + 256) >> 5, o1 = tid & 31;                                       \
        cp16(&As[sst][c1][o1 * 4],                                                      \
             Ag + ((size_t)((tm0 + (c1 >> 1)) * 64 + (t16) * 2 + (c1 & 1)) * 32 + o1)); \
        cp16(&Bs[sst][c0][o0 * 4], Bg + ((size_t)((tn0 + c0) * 32 + (t16)) * 32 + o0)); \
        cp16(&Bs[sst][c1][o1 * 4], Bg + ((size_t)((tn0 + c1) * 32 + (t16)) * 32 + o1)); \
        asm volatile("cp.async.commit_group;");                                         \
    }

    float4 c4[4][4];
#pragma unroll
    for (int i = 0; i < 4; i++)
#pragma unroll
        for (int j = 0; j < 4; j++) c4[i][j] = make_float4(0.f, 0.f, 0.f, 0.f);

    OP_LOAD(0, 0);
    for (int t16 = 0; t16 < 32; t16++) {
        int s = t16 & 1;
        if (t16 + 1 < 32) {
            OP_LOAD(s ^ 1, t16 + 1);
            asm volatile("cp.async.wait_group 1;" ::: "memory");
        } else {
            asm volatile("cp.async.wait_group 0;" ::: "memory");
        }
        __syncthreads();
        uint4 bv[4];
#pragma unroll
        for (int j = 0; j < 4; j++)
            bv[j] = *(const uint4*)&Bs[s][wn * 4 + j][l * 4];
        {
            uint4 a[4];
#pragma unroll
            for (int i = 0; i < 4; i++)
                a[i] = *(const uint4*)&As[s][(wm * 4 + i) * 2][l * 4];
#pragma unroll
            for (int i = 0; i < 4; i++)
#pragma unroll
                for (int j = 0; j < 4; j++) mma8(c4[i][j], a[i], bv[j].x, bv[j].y);
#pragma unroll
            for (int i = 0; i < 4; i++)
                a[i] = *(const uint4*)&As[s][(wm * 4 + i) * 2 + 1][l * 4];
#pragma unroll
            for (int i = 0; i < 4; i++)
#pragma unroll
                for (int j = 0; j < 4; j++) mma8(c4[i][j], a[i], bv[j].z, bv[j].w);
        }
        __syncthreads();
    }

    // write p (natural layout) and accumulate per-thread channel partials
    float ps[8], pq[8];
#pragma unroll
    for (int t = 0; t < 8; t++) { ps[t] = 0.f; pq[t] = 0.f; }
#pragma unroll
    for (int i = 0; i < 4; i++)
#pragma unroll
        for (int j = 0; j < 4; j++) {
            int m = m0 + wm * 64 + i * 16 + g;
            int n = n0 + wn * 32 + j * 8 + 2 * qq;
            float4 v = c4[i][j];
            *(float2*)&g_p[(size_t)m * 256 + n] = make_float2(v.x, v.y);
            *(float2*)&g_p[(size_t)(m + 8) * 256 + n] = make_float2(v.z, v.w);
            ps[j * 2 + 0] += v.x + v.z;
            ps[j * 2 + 1] += v.y + v.w;
            pq[j * 2 + 0] += v.x * v.x + v.z * v.z;
            pq[j * 2 + 1] += v.y * v.y + v.w * v.w;
        }
#pragma unroll
    for (int mask = 4; mask <= 16; mask <<= 1)
#pragma unroll
        for (int t = 0; t < 8; t++) {
            ps[t] += __shfl_xor_sync(0xffffffffu, ps[t], mask);
            pq[t] += __shfl_xor_sync(0xffffffffu, pq[t], mask);
        }

    float* sred = &As[0][0][0];
    if (tid < 256) sred[tid] = 0.f;
    __syncthreads();
    if (l < 4) {
#pragma unroll
        for (int j = 0; j < 4; j++)
#pragma unroll
            for (int col = 0; col < 2; col++) {
                int ch = wn * 32 + j * 8 + 2 * l + col;
                atomicAdd(&sred[ch], ps[j * 2 + col]);
                atomicAdd(&sred[128 + ch], pq[j * 2 + col]);
            }
    }
    __syncthreads();
    if (tid < 128) atomicAdd(&g_sum[n0 + tid], sred[tid]);
    else if (tid < 256) atomicAdd(&g_sumsq[n0 + (tid - 128)], sred[tid]);
}

// ---------------- small kernels ----------------
__global__ void zero_stats() {
    g_sum[threadIdx.x] = 0.f;
    g_sumsq[threadIdx.x] = 0.f;
}

__global__ void bnprep_kernel(const float* __restrict__ gamma,
                              const float* __restrict__ beta) {
    int c = threadIdx.x;
    const float inv_nm = 1.0f / (float)(NB * NSQ);
    float mean = g_sum[c] * inv_nm;
    float var = g_sumsq[c] * inv_nm - mean * mean;
    float sc = gamma[c] * rsqrtf(var + 1e-5f);
    g_scale[c] = sc;
    g_shift[c] = beta[c] - mean * sc;
}

__global__ void __launch_bounds__(256) finalize_kernel(float* __restrict__ out) {
    int idx = blockIdx.x * 256 + threadIdx.x;
    int c = threadIdx.x;
    float y = g_p[idx] * g_scale[c] + g_shift[c];
    out[idx] = (y >= 0.f) ? y : 0.01f * y;
}

// ---------------- launch ----------------
extern "C" void kernel_launch(void* const* d_in, const int* in_sizes, int n_in,
                              void* d_out, int out_size) {
    const float* x     = (const float*)d_in[0];
    const float* q     = (const float*)d_in[1];
    const float* Wq    = (const float*)d_in[2];
    const float* Wk    = (const float*)d_in[3];
    const float* Wv    = (const float*)d_in[4];
    const float* Wp    = (const float*)d_in[5];
    const float* gamma = (const float*)d_in[6];
    const float* beta  = (const float*)d_in[7];
    float* out = (float*)d_out;

    zero_stats<<<1, 256>>>();
    repackA<<<4096, 256>>>(q, 0);
    repackA<<<4096, 256>>>(x, 1);
    repackW<<<dim3(128, 4), 256>>>(Wq, Wk, Wv, Wp);
    gemm_qkv_mma<<<dim3(4, 128, 3), 256>>>();
    attn_mma<<<dim3(NSQ / 64, NH, NB), 128>>>();
    outproj_mma<<<dim3(2, 128), 256>>>();
    bnprep_kernel<<<1, 256>>>(gamma, beta);
    finalize_kernel<<<NB * NSQ, 256>>>(out);
}

// round 10
// speedup vs baseline: 3.7562x; 1.0157x over previous
#include <cuda_runtime.h>
#include <math_constants.h>

#define NB   16
#define NSQ  1024
#define NSE  1024
#define NCIN 256
#define NH   8
#define NFD  512

// ---------------- scratch ----------------
static __device__ float g_qh[NB * NSQ * NFD];
static __device__ float g_kh[NB * NSE * NFD];
static __device__ float g_vh[NB * NSE * NFD];
static __device__ float g_o [NB * NSQ * NFD];    // A-frag layout (tf32 bits)
static __device__ float g_p [NB * NSQ * NCIN];
static __device__ float g_qA[NB * NSQ * NCIN];
static __device__ float g_xA[NB * NSE * NCIN];
static __device__ float g_wqB[NFD * NCIN];
static __device__ float g_wkB[NFD * NCIN];
static __device__ float g_wvB[NFD * NCIN];
static __device__ float g_wpB[NCIN * NFD];
static __device__ float g_sum[NCIN];
static __device__ float g_sumsq[NCIN];
static __device__ float g_scale[NCIN];
static __device__ float g_shift[NCIN];

__device__ __forceinline__ void cp16(void* dst, const void* src) {
    unsigned d = (unsigned)__cvta_generic_to_shared(dst);
    asm volatile("cp.async.ca.shared.global [%0], [%1], 16;" :: "r"(d), "l"(src));
}

__device__ __forceinline__ unsigned tf32r(float x) {
    unsigned u;
    asm("cvt.rna.tf32.f32 %0, %1;" : "=r"(u) : "f"(x));
    return u;
}

__device__ __forceinline__ void mma8(float4& d, uint4 a, unsigned b0, unsigned b1) {
    asm volatile(
        "mma.sync.aligned.m16n8k8.row.col.f32.tf32.tf32.f32 "
        "{%0,%1,%2,%3}, {%4,%5,%6,%7}, {%8,%9}, {%0,%1,%2,%3};"
        : "+f"(d.x), "+f"(d.y), "+f"(d.z), "+f"(d.w)
        : "r"(a.x), "r"(a.y), "r"(a.z), "r"(a.w), "r"(b0), "r"(b1));
}

// ---------------- repack: activations -> A-frag (K=256), tf32-rounded ----------------
__global__ void __launch_bounds__(256) repackA(const float* __restrict__ qin,
                                               const float* __restrict__ xin) {
    int which = blockIdx.y;
    const float* in = which ? xin : qin;
    unsigned* out = (unsigned*)(which ? g_xA : g_qA);
    int u = blockIdx.x * 256 + threadIdx.x;
    int lane = u & 31, tile = u >> 5;
    int tk = tile & 31, tm = tile >> 5;
    int m = tm * 16 + (lane >> 2), k = tk * 8 + (lane & 3);
    const float* p = in + (size_t)m * 256 + k;
    uint4 v;
    v.x = tf32r(p[0]);
    v.y = tf32r(p[8 * 256]);
    v.z = tf32r(p[4]);
    v.w = tf32r(p[8 * 256 + 4]);
    ((uint4*)out)[u] = v;
}

// ---------------- repack: weights -> B-frag + zero stats ----------------
__global__ void __launch_bounds__(256) repackW(const float* __restrict__ Wq,
                                              const float* __restrict__ Wk,
                                              const float* __restrict__ Wv,
                                              const float* __restrict__ Wp) {
    if (blockIdx.x == 0 && blockIdx.y == 0) {
        g_sum[threadIdx.x] = 0.f;
        g_sumsq[threadIdx.x] = 0.f;
    }
    int which = blockIdx.y;
    const float* in = (which == 0) ? Wq : (which == 1) ? Wk : (which == 2) ? Wv : Wp;
    unsigned* out = (unsigned*)((which == 0) ? g_wqB : (which == 1) ? g_wkB
                                : (which == 2) ? g_wvB : g_wpB);
    int K = (which == 3) ? 512 : 256;
    int u = blockIdx.x * 256 + threadIdx.x;
    int lane = u & 31, chunk = u >> 5;
    int kp = K >> 4;
    int tkp = chunk % kp, tn = chunk / kp;
    int n = tn * 8 + (lane >> 2), kb = tkp * 16 + (lane & 3);
    const float* p = in + (size_t)n * K + kb;
    uint4 v;
    v.x = tf32r(p[0]);
    v.y = tf32r(p[4]);
    v.z = tf32r(p[8]);
    v.w = tf32r(p[12]);
    ((uint4*)out)[u] = v;
}

// scatter one QKV value into attn's fragment layouts
__device__ __forceinline__ void scatter_qkv(unsigned* out, int z, int m, int n, float val) {
    int b = m >> 10, s = m & 1023;
    int h = n >> 6, d = n & 63;
    size_t base = (size_t)(b * 8 + h) << 16;
    size_t ad;
    unsigned bits;
    if (z == 0) {
        bits = tf32r(val * 0.125f);
        ad = base + (size_t)(((s >> 4) * 8 + (d >> 3)) << 7)
             + (((s & 7) * 4 + (d & 3)) << 2) + ((s >> 3) & 1) + (((d >> 2) & 1) << 1);
    } else if (z == 1) {
        bits = tf32r(val);
        ad = base + (size_t)((s >> 3) << 9) + ((d >> 4) << 7)
             + (((s & 7) * 4 + (d & 3)) << 2) + (((d >> 3) & 1) << 1) + ((d >> 2) & 1);
    } else {
        bits = tf32r(val);
        ad = base + (size_t)((s >> 6) << 12) + ((d >> 3) << 9) + (((s >> 4) & 3) << 7)
             + (((d & 7) * 4 + (s & 3)) << 2) + (((s >> 3) & 1) << 1) + ((s >> 2) & 1);
    }
    out[ad] = bits;
}

// ---------------- QKV projection on tensor cores (K=256) ----------------
__global__ void __launch_bounds__(256, 2) gemm_qkv_mma() {
    __shared__ float As[2][16][128];
    __shared__ float Bs[2][16][128];
    const int tid = threadIdx.x;
    const int w = tid >> 5, l = tid & 31;
    const int wm = w & 1, wn = w >> 1;
    const int g = l >> 2, qq = l & 3;
    const int z = blockIdx.z;
    const int m0 = blockIdx.y * 128, n0 = blockIdx.x * 128;
    const int tm0 = blockIdx.y * 8, tn0 = blockIdx.x * 16;

    const uint4* Ag = (const uint4*)((z == 0) ? g_qA : g_xA);
    const uint4* Bg = (const uint4*)((z == 0) ? g_wqB : (z == 1) ? g_wkB : g_wvB);

#define QKV_LOAD(sst, t16)                                                              \
    {                                                                                   \
        int c0 = tid >> 5, o0 = tid & 31;                                               \
        cp16(&As[sst][c0][o0 * 4],                                                      \
             Ag + ((size_t)((tm0 + (c0 >> 1)) * 32 + (t16) * 2 + (c0 & 1)) * 32 + o0)); \
        int c1 = (tid + 256) >> 5, o1 = tid & 31;                                       \
        cp16(&As[sst][c1][o1 * 4],                                                      \
             Ag + ((size_t)((tm0 + (c1 >> 1)) * 32 + (t16) * 2 + (c1 & 1)) * 32 + o1)); \
        cp16(&Bs[sst][c0][o0 * 4], Bg + ((size_t)((tn0 + c0) * 16 + (t16)) * 32 + o0)); \
        cp16(&Bs[sst][c1][o1 * 4], Bg + ((size_t)((tn0 + c1) * 16 + (t16)) * 32 + o1)); \
        asm volatile("cp.async.commit_group;");                                         \
    }

    float4 c4[4][4];
#pragma unroll
    for (int i = 0; i < 4; i++)
#pragma unroll
        for (int j = 0; j < 4; j++) c4[i][j] = make_float4(0.f, 0.f, 0.f, 0.f);

    QKV_LOAD(0, 0);
    for (int t16 = 0; t16 < 16; t16++) {
        int s = t16 & 1;
        if (t16 + 1 < 16) {
            QKV_LOAD(s ^ 1, t16 + 1);
            asm volatile("cp.async.wait_group 1;" ::: "memory");
        } else {
            asm volatile("cp.async.wait_group 0;" ::: "memory");
        }
        __syncthreads();
        uint4 bv[4];
#pragma unroll
        for (int j = 0; j < 4; j++)
            bv[j] = *(const uint4*)&Bs[s][wn * 4 + j][l * 4];
        {
            uint4 a[4];
#pragma unroll
            for (int i = 0; i < 4; i++)
                a[i] = *(const uint4*)&As[s][(wm * 4 + i) * 2][l * 4];
#pragma unroll
            for (int i = 0; i < 4; i++)
#pragma unroll
                for (int j = 0; j < 4; j++) mma8(c4[i][j], a[i], bv[j].x, bv[j].y);
#pragma unroll
            for (int i = 0; i < 4; i++)
                a[i] = *(const uint4*)&As[s][(wm * 4 + i) * 2 + 1][l * 4];
#pragma unroll
            for (int i = 0; i < 4; i++)
#pragma unroll
                for (int j = 0; j < 4; j++) mma8(c4[i][j], a[i], bv[j].z, bv[j].w);
        }
        __syncthreads();
    }

    unsigned* out = (unsigned*)((z == 0) ? g_qh : (z == 1) ? g_kh : g_vh);
#pragma unroll
    for (int i = 0; i < 4; i++)
#pragma unroll
        for (int j = 0; j < 4; j++) {
            int m = m0 + wm * 64 + i * 16 + g;
            int n = n0 + wn * 32 + j * 8 + 2 * qq;
            scatter_qkv(out, z, m, n, c4[i][j].x);
            scatter_qkv(out, z, m, n + 1, c4[i][j].y);
            scatter_qkv(out, z, m + 8, n, c4[i][j].z);
            scatter_qkv(out, z, m + 8, n + 1, c4[i][j].w);
        }
}

// ---------------- flash attention: 8 warps, 128 q-rows, double-buffered K/V ----------------
extern __shared__ unsigned smA[];   // Ks[2][4096] | Vs[2][4096] | Pb[8][1024]  = 96 KB

__global__ void __launch_bounds__(256, 2) attn_mma() {
    unsigned* Ks = smA;                 // [buf][4096]
    unsigned* Vs = smA + 8192;
    const int tid = threadIdx.x;
    const int w = tid >> 5, l = tid & 31;
    unsigned* Pw = smA + 16384 + w * 1024;
    const int g = l >> 2, qq = l & 3;
    const int b = blockIdx.z, h = blockIdx.y;
    const int q0 = blockIdx.x * 128;
    const int rt = (q0 >> 4) + w;

    const unsigned* Qg = (const unsigned*)g_qh + (size_t)(((b * 8 + h) * 64 + rt) * 8) * 128;
    uint4 qa[8];
#pragma unroll
    for (int kk = 0; kk < 8; kk++)
        qa[kk] = *(const uint4*)(Qg + kk * 128 + l * 4);

    const unsigned* Kg = (const unsigned*)g_kh + (size_t)((b * 8 + h) * 16) * 4096;
    const unsigned* Vg = (const unsigned*)g_vh + (size_t)((b * 8 + h) * 16) * 4096;

#define ATT_LOAD(buf, kt)                                                        \
    {                                                                            \
        _Pragma("unroll")                                                        \
        for (int i = 0; i < 4; i++) {                                            \
            int u = i * 256 + tid;                                               \
            cp16(&Ks[(buf) * 4096 + u * 4], Kg + (size_t)(kt) * 4096 + u * 4);   \
            cp16(&Vs[(buf) * 4096 + u * 4], Vg + (size_t)(kt) * 4096 + u * 4);   \
        }                                                                        \
        asm volatile("cp.async.commit_group;");                                  \
    }

    float4 o[8];
#pragma unroll
    for (int nt = 0; nt < 8; nt++) o[nt] = make_float4(0.f, 0.f, 0.f, 0.f);
    float m0_ = -CUDART_INF_F, m1_ = -CUDART_INF_F, l0_ = 0.f, l1_ = 0.f;

    ATT_LOAD(0, 0);
    for (int kt = 0; kt < 16; kt++) {
        const int buf = kt & 1;
        if (kt + 1 < 16) {
            ATT_LOAD(buf ^ 1, kt + 1);
            asm volatile("cp.async.wait_group 1;" ::: "memory");
        } else {
            asm volatile("cp.async.wait_group 0;" ::: "memory");
        }
        __syncthreads();
        const unsigned* Kb = &Ks[buf * 4096];
        const unsigned* Vb = &Vs[buf * 4096];

        float4 s[8];
#pragma unroll
        for (int nt = 0; nt < 8; nt++) {
            s[nt] = make_float4(0.f, 0.f, 0.f, 0.f);
            uint4 k0 = *(const uint4*)&Kb[nt * 512 + (0 * 32 + l) * 4];
            uint4 k1 = *(const uint4*)&Kb[nt * 512 + (1 * 32 + l) * 4];
            uint4 k2 = *(const uint4*)&Kb[nt * 512 + (2 * 32 + l) * 4];
            uint4 k3 = *(const uint4*)&Kb[nt * 512 + (3 * 32 + l) * 4];
            mma8(s[nt], qa[0], k0.x, k0.y); mma8(s[nt], qa[1], k0.z, k0.w);
            mma8(s[nt], qa[2], k1.x, k1.y); mma8(s[nt], qa[3], k1.z, k1.w);
            mma8(s[nt], qa[4], k2.x, k2.y); mma8(s[nt], qa[5], k2.z, k2.w);
            mma8(s[nt], qa[6], k3.x, k3.y); mma8(s[nt], qa[7], k3.z, k3.w);
        }

        float mx0 = fmaxf(s[0].x, s[0].y), mx1 = fmaxf(s[0].z, s[0].w);
#pragma unroll
        for (int nt = 1; nt < 8; nt++) {
            mx0 = fmaxf(mx0, fmaxf(s[nt].x, s[nt].y));
            mx1 = fmaxf(mx1, fmaxf(s[nt].z, s[nt].w));
        }
        mx0 = fmaxf(mx0, __shfl_xor_sync(0xffffffffu, mx0, 1));
        mx0 = fmaxf(mx0, __shfl_xor_sync(0xffffffffu, mx0, 2));
        mx1 = fmaxf(mx1, __shfl_xor_sync(0xffffffffu, mx1, 1));
        mx1 = fmaxf(mx1, __shfl_xor_sync(0xffffffffu, mx1, 2));
        float nm0 = fmaxf(m0_, mx0), nm1 = fmaxf(m1_, mx1);
        float f0 = __expf(m0_ - nm0), f1 = __expf(m1_ - nm1);
        m0_ = nm0; m1_ = nm1;

        float rs0 = 0.f, rs1 = 0.f;
        const int cA = 4 * g + ((2 * qq) & 3);
        const int cB = 4 * g + ((2 * qq + 1) & 3);
        const int phA = (cA ^ (cA >> 3)) * 4 + 2 * (qq >> 1);
        const int phB = (cB ^ (cB >> 3)) * 4 + 2 * (qq >> 1);
#pragma unroll
        for (int nt = 0; nt < 8; nt++) {
            unsigned p0 = tf32r(__expf(s[nt].x - nm0));
            unsigned p1 = tf32r(__expf(s[nt].y - nm0));
            unsigned p2 = tf32r(__expf(s[nt].z - nm1));
            unsigned p3 = tf32r(__expf(s[nt].w - nm1));
            rs0 += __uint_as_float(p0) + __uint_as_float(p1);
            rs1 += __uint_as_float(p2) + __uint_as_float(p3);
            uint2 vA; vA.x = p0; vA.y = p2;
            uint2 vB; vB.x = p1; vB.y = p3;
            *(uint2*)&Pw[nt * 128 + phA] = vA;
            *(uint2*)&Pw[nt * 128 + phB] = vB;
        }
        rs0 += __shfl_xor_sync(0xffffffffu, rs0, 1);
        rs0 += __shfl_xor_sync(0xffffffffu, rs0, 2);
        rs1 += __shfl_xor_sync(0xffffffffu, rs1, 1);
        rs1 += __shfl_xor_sync(0xffffffffu, rs1, 2);
        l0_ = l0_ * f0 + rs0;
        l1_ = l1_ * f1 + rs1;

#pragma unroll
        for (int nt = 0; nt < 8; nt++) {
            o[nt].x *= f0; o[nt].y *= f0; o[nt].z *= f1; o[nt].w *= f1;
        }
        __syncwarp();

        const int cr = (l ^ (l >> 3)) * 4;
        uint4 pa[8];
#pragma unroll
        for (int kk = 0; kk < 8; kk++)
            pa[kk] = *(const uint4*)&Pw[kk * 128 + cr];

#pragma unroll
        for (int nt = 0; nt < 8; nt++) {
            uint4 v0 = *(const uint4*)&Vb[nt * 512 + (0 * 32 + l) * 4];
            uint4 v1 = *(const uint4*)&Vb[nt * 512 + (1 * 32 + l) * 4];
            uint4 v2 = *(const uint4*)&Vb[nt * 512 + (2 * 32 + l) * 4];
            uint4 v3 = *(const uint4*)&Vb[nt * 512 + (3 * 32 + l) * 4];
            mma8(o[nt], pa[0], v0.x, v0.y); mma8(o[nt], pa[1], v0.z, v0.w);
            mma8(o[nt], pa[2], v1.x, v1.y); mma8(o[nt], pa[3], v1.z, v1.w);
            mma8(o[nt], pa[4], v2.x, v2.y); mma8(o[nt], pa[5], v2.z, v2.w);
            mma8(o[nt], pa[6], v3.x, v3.y); mma8(o[nt], pa[7], v3.z, v3.w);
        }
        __syncthreads();
    }

    float inv0 = 1.0f / l0_, inv1 = 1.0f / l1_;
    unsigned* Oo = (unsigned*)g_o;
    const int tmrow = b * 64 + (q0 >> 4) + w;
#pragma unroll
    for (int nt = 0; nt < 8; nt++) {
        int k0 = h * 64 + nt * 8 + 2 * qq;
        int tk = k0 >> 3;
        size_t toff = (size_t)(tmrow * 64 + tk) * 128;
        int rbase = ((k0 >> 2) & 1) * 2;
        uint2 vx; vx.x = tf32r(o[nt].x * inv0); vx.y = tf32r(o[nt].z * inv1);
        *(uint2*)&Oo[toff + (g * 4 + (k0 & 3)) * 4 + rbase] = vx;
        uint2 vy; vy.x = tf32r(o[nt].y * inv0); vy.y = tf32r(o[nt].w * inv1);
        *(uint2*)&Oo[toff + (g * 4 + ((k0 + 1) & 3)) * 4 + rbase] = vy;
    }
}

// ---------------- output projection on tensor cores (K=512) + BN stats ----------------
__global__ void __launch_bounds__(256, 2) outproj_mma() {
    __shared__ float As[2][16][128];
    __shared__ float Bs[2][16][128];
    const int tid = threadIdx.x;
    const int w = tid >> 5, l = tid & 31;
    const int wm = w & 1, wn = w >> 1;
    const int g = l >> 2, qq = l & 3;
    const int m0 = blockIdx.y * 128, n0 = blockIdx.x * 128;
    const int tm0 = blockIdx.y * 8, tn0 = blockIdx.x * 16;

    const uint4* Ag = (const uint4*)g_o;
    const uint4* Bg = (const uint4*)g_wpB;

#define OP_LOAD(sst, t16)                                                               \
    {                                                                                   \
        int c0 = tid >> 5, o0 = tid & 31;                                               \
        cp16(&As[sst][c0][o0 * 4],                                                      \
             Ag + ((size_t)((tm0 + (c0 >> 1)) * 64 + (t16) * 2 + (c0 & 1)) * 32 + o0)); \
        int c1 = (tid + 256) >> 5, o1 = tid & 31;                                       \
        cp16(&As[sst][c1][o1 * 4],                                                      \
             Ag + ((size_t)((tm0 + (c1 >> 1)) * 64 + (t16) * 2 + (c1 & 1)) * 32 + o1)); \
        cp16(&Bs[sst][c0][o0 * 4], Bg + ((size_t)((tn0 + c0) * 32 + (t16)) * 32 + o0)); \
        cp16(&Bs[sst][c1][o1 * 4], Bg + ((size_t)((tn0 + c1) * 32 + (t16)) * 32 + o1)); \
        asm volatile("cp.async.commit_group;");                                         \
    }

    float4 c4[4][4];
#pragma unroll
    for (int i = 0; i < 4; i++)
#pragma unroll
        for (int j = 0; j < 4; j++) c4[i][j] = make_float4(0.f, 0.f, 0.f, 0.f);

    OP_LOAD(0, 0);
    for (int t16 = 0; t16 < 32; t16++) {
        int s = t16 & 1;
        if (t16 + 1 < 32) {
            OP_LOAD(s ^ 1, t16 + 1);
            asm volatile("cp.async.wait_group 1;" ::: "memory");
        } else {
            asm volatile("cp.async.wait_group 0;" ::: "memory");
        }
        __syncthreads();
        uint4 bv[4];
#pragma unroll
        for (int j = 0; j < 4; j++)
            bv[j] = *(const uint4*)&Bs[s][wn * 4 + j][l * 4];
        {
            uint4 a[4];
#pragma unroll
            for (int i = 0; i < 4; i++)
                a[i] = *(const uint4*)&As[s][(wm * 4 + i) * 2][l * 4];
#pragma unroll
            for (int i = 0; i < 4; i++)
#pragma unroll
                for (int j = 0; j < 4; j++) mma8(c4[i][j], a[i], bv[j].x, bv[j].y);
#pragma unroll
            for (int i = 0; i < 4; i++)
                a[i] = *(const uint4*)&As[s][(wm * 4 + i) * 2 + 1][l * 4];
#pragma unroll
            for (int i = 0; i < 4; i++)
#pragma unroll
                for (int j = 0; j < 4; j++) mma8(c4[i][j], a[i], bv[j].z, bv[j].w);
        }
        __syncthreads();
    }

    float ps[8], pq[8];
#pragma unroll
    for (int t = 0; t < 8; t++) { ps[t] = 0.f; pq[t] = 0.f; }
#pragma unroll
    for (int i = 0; i < 4; i++)
#pragma unroll
        for (int j = 0; j < 4; j++) {
            int m = m0 + wm * 64 + i * 16 + g;
            int n = n0 + wn * 32 + j * 8 + 2 * qq;
            float4 v = c4[i][j];
            *(float2*)&g_p[(size_t)m * 256 + n] = make_float2(v.x, v.y);
            *(float2*)&g_p[(size_t)(m + 8) * 256 + n] = make_float2(v.z, v.w);
            ps[j * 2 + 0] += v.x + v.z;
            ps[j * 2 + 1] += v.y + v.w;
            pq[j * 2 + 0] += v.x * v.x + v.z * v.z;
            pq[j * 2 + 1] += v.y * v.y + v.w * v.w;
        }
#pragma unroll
    for (int mask = 4; mask <= 16; mask <<= 1)
#pragma unroll
        for (int t = 0; t < 8; t++) {
            ps[t] += __shfl_xor_sync(0xffffffffu, ps[t], mask);
            pq[t] += __shfl_xor_sync(0xffffffffu, pq[t], mask);
        }

    float* sred = &As[0][0][0];
    if (tid < 256) sred[tid] = 0.f;
    __syncthreads();
    if (l < 4) {
#pragma unroll
        for (int j = 0; j < 4; j++)
#pragma unroll
            for (int col = 0; col < 2; col++) {
                int ch = wn * 32 + j * 8 + 2 * l + col;
                atomicAdd(&sred[ch], ps[j * 2 + col]);
                atomicAdd(&sred[128 + ch], pq[j * 2 + col]);
            }
    }
    __syncthreads();
    if (tid < 128) atomicAdd(&g_sum[n0 + tid], sred[tid]);
    else if (tid < 256) atomicAdd(&g_sumsq[n0 + (tid - 128)], sred[tid]);
}

// ---------------- small kernels ----------------
__global__ void bnprep_kernel(const float* __restrict__ gamma,
                              const float* __restrict__ beta) {
    int c = threadIdx.x;
    const float inv_nm = 1.0f / (float)(NB * NSQ);
    float mean = g_sum[c] * inv_nm;
    float var = g_sumsq[c] * inv_nm - mean * mean;
    float sc = gamma[c] * rsqrtf(var + 1e-5f);
    g_scale[c] = sc;
    g_shift[c] = beta[c] - mean * sc;
}

__global__ void __launch_bounds__(256) finalize_kernel(float* __restrict__ out) {
    int idx = blockIdx.x * 256 + threadIdx.x;
    int c = threadIdx.x;
    float y = g_p[idx] * g_scale[c] + g_shift[c];
    out[idx] = (y >= 0.f) ? y : 0.01f * y;
}

// ---------------- launch ----------------
extern "C" void kernel_launch(void* const* d_in, const int* in_sizes, int n_in,
                              void* d_out, int out_size) {
    const float* x     = (const float*)d_in[0];
    const float* q     = (const float*)d_in[1];
    const float* Wq    = (const float*)d_in[2];
    const float* Wk    = (const float*)d_in[3];
    const float* Wv    = (const float*)d_in[4];
    const float* Wp    = (const float*)d_in[5];
    const float* gamma = (const float*)d_in[6];
    const float* beta  = (const float*)d_in[7];
    float* out = (float*)d_out;

    cudaFuncSetAttribute(attn_mma, cudaFuncAttributeMaxDynamicSharedMemorySize, 98304);

    repackA<<<dim3(4096, 2), 256>>>(q, x);
    repackW<<<dim3(128, 4), 256>>>(Wq, Wk, Wv, Wp);
    gemm_qkv_mma<<<dim3(4, 128, 3), 256>>>();
    attn_mma<<<dim3(NSQ / 128, NH, NB), 256, 98304>>>();
    outproj_mma<<<dim3(2, 128), 256>>>();
    bnprep_kernel<<<1, 256>>>(gamma, beta);
    finalize_kernel<<<NB * NSQ, 256>>>(out);
}